// round 3
// baseline (speedup 1.0000x reference)
#include <cuda_runtime.h>
#include <cstdint>

#define NROW 512
#define HH 8
#define DD 32
#define INNER 256
#define ED 64
#define SCALE 0.17677669529663687f  // 1/sqrt(32)
#define ESTRIDE 68                  // padded row stride (floats) for conflict-free f4
#define ESMEM (NROW * ESTRIDE * 4)  // 139264 B dynamic smem for one full edge row

// Scratch (device globals; no allocation in kernel_launch).
__device__ float g_q[NROW * INNER];
__device__ float g_k[NROW * INNER];
__device__ float g_v[NROW * INNER];
__device__ float g_t[NROW * HH * ED];      // [i][h][c]  t = We_h^T q_{h,i}
__device__ float g_qbe[NROW * HH];         // q_{h,i} . be_h
__device__ float g_simqk[HH * NROW * NROW];
__device__ float g_attn[HH * NROW * NROW];
__device__ float g_agg[NROW * HH * ED];    // [i][h][c]
__device__ float g_rowsum[HH * NROW];      // 1 if any neighbor, else 0

__device__ __forceinline__ void cp16(unsigned int daddr, const void* gptr) {
    asm volatile("cp.async.cg.shared.global [%0], [%1], 16;\n"
                 :: "r"(daddr), "l"(gptr));
}

// ---------------------------------------------------------------------------
// Kernel A: q/k/v projections + t = We_h^T q + qbe.  4 rows per block.
// ---------------------------------------------------------------------------
__global__ __launch_bounds__(256) void proj_kernel(
    const float* __restrict__ nodes,
    const float* __restrict__ Wq, const float* __restrict__ bq,
    const float* __restrict__ Wk, const float* __restrict__ bk,
    const float* __restrict__ Wv, const float* __restrict__ bv,
    const float* __restrict__ We, const float* __restrict__ be)
{
    __shared__ float node_s[4][128];
    __shared__ float q_s[4][INNER];
    const int t = threadIdx.x;
    const int i0 = blockIdx.x * 4;

    for (int idx = t; idx < 4 * 128; idx += 256)
        node_s[idx >> 7][idx & 127] = nodes[i0 * 128 + idx];
    __syncthreads();

    float aq[4], ak[4], av[4];
    const float bqv = bq[t], bkv = bk[t], bvv = bv[t];
#pragma unroll
    for (int r = 0; r < 4; r++) { aq[r] = bqv; ak[r] = bkv; av[r] = bvv; }

    for (int k = 0; k < 128; k++) {
        const float wq = Wq[k * INNER + t];
        const float wk = Wk[k * INNER + t];
        const float wv = Wv[k * INNER + t];
#pragma unroll
        for (int r = 0; r < 4; r++) {
            const float nv = node_s[r][k];
            aq[r] = fmaf(nv, wq, aq[r]);
            ak[r] = fmaf(nv, wk, ak[r]);
            av[r] = fmaf(nv, wv, av[r]);
        }
    }
#pragma unroll
    for (int r = 0; r < 4; r++) {
        g_q[(i0 + r) * INNER + t] = aq[r];
        g_k[(i0 + r) * INNER + t] = ak[r];
        g_v[(i0 + r) * INNER + t] = av[r];
        q_s[r][t] = aq[r];
    }
    __syncthreads();

    // t[i][h][c] = sum_d We[c, h*32+d] * q[i, h*32+d]
    for (int idx = t; idx < HH * ED; idx += 256) {
        const int h = idx >> 6, c = idx & 63;
        float acc[4] = {0.f, 0.f, 0.f, 0.f};
        const float* wrow = We + c * INNER + h * DD;
#pragma unroll
        for (int d = 0; d < DD; d++) {
            const float w = wrow[d];
#pragma unroll
            for (int r = 0; r < 4; r++)
                acc[r] = fmaf(w, q_s[r][h * DD + d], acc[r]);
        }
#pragma unroll
        for (int r = 0; r < 4; r++)
            g_t[(i0 + r) * (HH * ED) + idx] = acc[r];
    }

    if (t < 4 * HH) {
        const int r = t >> 3, h = t & 7;
        float s = 0.f;
#pragma unroll
        for (int d = 0; d < DD; d++)
            s = fmaf(q_s[r][h * DD + d], be[h * DD + d], s);
        g_qbe[(i0 + r) * HH + h] = s;
    }
}

// ---------------------------------------------------------------------------
// Kernel QK: simqk[h][i][j] = (q_h[i].k_h[j] + qbe[i][h]) * SCALE
// ---------------------------------------------------------------------------
__global__ __launch_bounds__(256) void qk_kernel()
{
    __shared__ float q_s[32][33];
    __shared__ float k_s[32][33];
    const int t = threadIdx.x;
    const int j0 = blockIdx.x * 32;
    const int i0 = blockIdx.y * 32;
    const int h  = blockIdx.z;

    {
        const int r = t >> 3, c4 = (t & 7) * 4;
        const float4 qv = *(const float4*)&g_q[(i0 + r) * INNER + h * DD + c4];
        q_s[r][c4 + 0] = qv.x; q_s[r][c4 + 1] = qv.y;
        q_s[r][c4 + 2] = qv.z; q_s[r][c4 + 3] = qv.w;
        const float4 kv = *(const float4*)&g_k[(j0 + r) * INNER + h * DD + c4];
        k_s[r][c4 + 0] = kv.x; k_s[r][c4 + 1] = kv.y;
        k_s[r][c4 + 2] = kv.z; k_s[r][c4 + 3] = kv.w;
    }
    __syncthreads();

    const int tx = t & 31, ty = t >> 5;
    float acc[4] = {0.f, 0.f, 0.f, 0.f};
#pragma unroll
    for (int d = 0; d < 32; d++) {
        const float kv = k_s[tx][d];
#pragma unroll
        for (int m = 0; m < 4; m++)
            acc[m] = fmaf(q_s[ty + m * 8][d], kv, acc[m]);
    }
#pragma unroll
    for (int m = 0; m < 4; m++) {
        const int i = i0 + ty + m * 8;
        g_simqk[((size_t)h * NROW + i) * NROW + j0 + tx] =
            (acc[m] + g_qbe[i * HH + h]) * SCALE;
    }
}

// ---------------------------------------------------------------------------
// Kernel B: per node-row i — edge scores + softmax + edge aggregation.
// One block per row (512 blocks, 512 threads). Full 512x64 edge row persisted
// in dynamic smem (cp.async prefetch, 4 commit groups), read ONCE from gmem.
// ---------------------------------------------------------------------------
__global__ __launch_bounds__(512, 1) void attn_kernel(
    const float* __restrict__ edges, const int* __restrict__ adj)
{
    extern __shared__ __align__(16) float e_s[];      // [512][ESTRIDE]
    __shared__ __align__(16) float t_s[HH * ESTRIDE];
    __shared__ float sim_s[HH * NROW];                // sim, then attn (16 KB)

    const int t = threadIdx.x;
    const int i = blockIdx.x;

    // prefetch all edges for row i: 4 groups of 128 j-rows
    {
        const int c4 = t & 15, r0 = t >> 4;           // r0: 0..31
        const float* gsrc = edges + (size_t)i * NROW * ED;
        unsigned int sbase = (unsigned int)__cvta_generic_to_shared(e_s);
#pragma unroll
        for (int g = 0; g < 4; g++) {
#pragma unroll
            for (int it = 0; it < 4; it++) {
                const int row = g * 128 + it * 32 + r0;
                cp16(sbase + (unsigned int)(row * ESTRIDE + c4 * 4) * 4,
                     gsrc + (size_t)row * ED + c4 * 4);
            }
            asm volatile("cp.async.commit_group;\n" ::: "memory");
        }
    }

    for (int idx = t; idx < HH * ED; idx += 512)
        t_s[(idx >> 6) * ESTRIDE + (idx & 63)] = g_t[i * (HH * ED) + idx];

    // ---- pass 1: sim[h][j] = (edges_ij . t[h]) * SCALE + simqk ----
    const int hh = t >> 7;        // 0..3 (heads hh and hh+4)
    const int jj = t & 127;
    for (int ch = 0; ch < 4; ch++) {
        if      (ch == 0) asm volatile("cp.async.wait_group 3;\n" ::: "memory");
        else if (ch == 1) asm volatile("cp.async.wait_group 2;\n" ::: "memory");
        else if (ch == 2) asm volatile("cp.async.wait_group 1;\n" ::: "memory");
        else              asm volatile("cp.async.wait_group 0;\n" ::: "memory");
        __syncthreads();

        const int j = ch * 128 + jj;
        float acc0 = 0.f, acc1 = 0.f;
        const float4* ep  = (const float4*)&e_s[j * ESTRIDE];
        const float4* ta4 = (const float4*)&t_s[hh * ESTRIDE];
        const float4* tb4 = (const float4*)&t_s[(hh + 4) * ESTRIDE];
#pragma unroll
        for (int c = 0; c < 16; c++) {
            const float4 e4 = ep[c];
            const float4 ta = ta4[c];
            const float4 tb = tb4[c];
            acc0 = fmaf(e4.x, ta.x, acc0); acc0 = fmaf(e4.y, ta.y, acc0);
            acc0 = fmaf(e4.z, ta.z, acc0); acc0 = fmaf(e4.w, ta.w, acc0);
            acc1 = fmaf(e4.x, tb.x, acc1); acc1 = fmaf(e4.y, tb.y, acc1);
            acc1 = fmaf(e4.z, tb.z, acc1); acc1 = fmaf(e4.w, tb.w, acc1);
        }
        sim_s[hh * NROW + j] =
            fmaf(acc0, SCALE, g_simqk[((size_t)hh * NROW + i) * NROW + j]);
        sim_s[(hh + 4) * NROW + j] =
            fmaf(acc1, SCALE, g_simqk[((size_t)(hh + 4) * NROW + i) * NROW + j]);
    }
    __syncthreads();

    // ---- softmax (row-constant mean shift cancels exactly; values O(0.1)) ----
    {
        const int w = t >> 5, lane = t & 31;          // warps 0..7 = heads
        if (w < 8) {
            float part = 0.f;
#pragma unroll
            for (int k = 0; k < 16; k++) {
                const int j = lane + k * 32;
                const float s = sim_s[w * NROW + j];
                const int a = adj[i * NROW + j];
                const float ex = a ? __expf(s) : 0.f;
                sim_s[w * NROW + j] = ex;
                part += ex;
            }
#pragma unroll
            for (int o = 16; o > 0; o >>= 1)
                part += __shfl_xor_sync(0xffffffffu, part, o);
            const float inv = part > 0.f ? 1.f / part : 0.f;
            if (lane == 0) g_rowsum[w * NROW + i] = part > 0.f ? 1.f : 0.f;
#pragma unroll
            for (int k = 0; k < 16; k++) {
                const int j = lane + k * 32;
                const float a = sim_s[w * NROW + j] * inv;
                sim_s[w * NROW + j] = a;
                g_attn[((size_t)w * NROW + i) * NROW + j] = a;
            }
        }
    }
    __syncthreads();

    // ---- pass 2: agg[h][c] = sum_j attn[h][j] * edges[i][j][c]
    //      warp = c4-chunk, lane = j-offset; in-warp shuffle reduction ----
    {
        const int c4w = t >> 5;   // 0..15
        const int l   = t & 31;
        float4 acc[8];
#pragma unroll
        for (int h = 0; h < 8; h++) acc[h] = make_float4(0.f, 0.f, 0.f, 0.f);
#pragma unroll 4
        for (int kk = 0; kk < 16; kk++) {
            const int j = l + kk * 32;
            const float4 e4 = *(const float4*)&e_s[j * ESTRIDE + c4w * 4];
#pragma unroll
            for (int h = 0; h < 8; h++) {
                const float a = sim_s[h * NROW + j];
                acc[h].x = fmaf(a, e4.x, acc[h].x);
                acc[h].y = fmaf(a, e4.y, acc[h].y);
                acc[h].z = fmaf(a, e4.z, acc[h].z);
                acc[h].w = fmaf(a, e4.w, acc[h].w);
            }
        }
#pragma unroll
        for (int o = 16; o > 0; o >>= 1) {
#pragma unroll
            for (int h = 0; h < 8; h++) {
                acc[h].x += __shfl_xor_sync(0xffffffffu, acc[h].x, o);
                acc[h].y += __shfl_xor_sync(0xffffffffu, acc[h].y, o);
                acc[h].z += __shfl_xor_sync(0xffffffffu, acc[h].z, o);
                acc[h].w += __shfl_xor_sync(0xffffffffu, acc[h].w, o);
            }
        }
        if (l == 0) {
#pragma unroll
            for (int h = 0; h < 8; h++)
                *(float4*)&g_agg[i * (HH * ED) + h * ED + c4w * 4] = acc[h];
        }
    }
}

// ---------------------------------------------------------------------------
// Kernel C1: out = agg @ We + rowsum * be   (plain stores; runs BEFORE C2)
// ---------------------------------------------------------------------------
__global__ __launch_bounds__(256) void outbias_kernel(
    const float* __restrict__ We, const float* __restrict__ be,
    float* __restrict__ out)
{
    __shared__ float a_s[32 * 64];
    const int t = threadIdx.x;
    const int i0 = blockIdx.x * 32;
    const int h  = blockIdx.y;
    const int d  = t & 31;
    const int i4 = t >> 5;

#pragma unroll
    for (int f = 0; f < 2; f++) {
        const int idx = t * 2 + f;
        const int row = idx >> 4, c4 = idx & 15;
        *(float4*)&a_s[row * 64 + c4 * 4] =
            *(const float4*)&g_agg[(i0 + row) * (HH * ED) + h * ED + c4 * 4];
    }
    __syncthreads();

    float acc[4] = {0.f, 0.f, 0.f, 0.f};
#pragma unroll 8
    for (int c = 0; c < 64; c++) {
        const float w = We[c * INNER + h * DD + d];
#pragma unroll
        for (int m = 0; m < 4; m++)
            acc[m] = fmaf(a_s[(i4 + m * 8) * 64 + c], w, acc[m]);
    }
    const float bev = be[h * DD + d];
#pragma unroll
    for (int m = 0; m < 4; m++) {
        const int i = i0 + i4 + m * 8;
        out[i * INNER + h * DD + d] = fmaf(g_rowsum[h * NROW + i], bev, acc[m]);
    }
}

// ---------------------------------------------------------------------------
// Kernel C2: out += attn @ v, j split 4-ways, atomicAdd epilogue.
// grid (16 i-tiles, 8 heads, 4 j-splits) = 512 blocks.
// ---------------------------------------------------------------------------
__global__ __launch_bounds__(256) void outv_kernel(float* __restrict__ out)
{
    __shared__ float a_s[32 * 128];   // attn tile
    __shared__ float v_s[128 * 32];   // v tile
    const int t = threadIdx.x;
    const int i0 = blockIdx.x * 32;
    const int h  = blockIdx.y;
    const int j0 = blockIdx.z * 128;

#pragma unroll
    for (int f = 0; f < 4; f++) {
        const int idx = t + f * 256;          // 1024 float4s attn 32x128
        const int row = idx >> 5, c4 = idx & 31;
        *(float4*)&a_s[row * 128 + c4 * 4] =
            *(const float4*)&g_attn[((size_t)h * NROW + i0 + row) * NROW + j0 + c4 * 4];
    }
#pragma unroll
    for (int f = 0; f < 4; f++) {
        const int idx = t + f * 256;          // 1024 float4s v 128x32
        const int row = idx >> 3, c4 = idx & 7;
        *(float4*)&v_s[row * 32 + c4 * 4] =
            *(const float4*)&g_v[(j0 + row) * INNER + h * DD + c4 * 4];
    }
    __syncthreads();

    const int d  = t & 31;
    const int i4 = t >> 5;
    float acc[4] = {0.f, 0.f, 0.f, 0.f};
#pragma unroll 8
    for (int j = 0; j < 128; j++) {
        const float vv = v_s[j * 32 + d];
#pragma unroll
        for (int m = 0; m < 4; m++)
            acc[m] = fmaf(a_s[(i4 + m * 8) * 128 + j], vv, acc[m]);
    }
#pragma unroll
    for (int m = 0; m < 4; m++)
        atomicAdd(&out[(i0 + i4 + m * 8) * INNER + h * DD + d], acc[m]);
}

// ---------------------------------------------------------------------------
extern "C" void kernel_launch(void* const* d_in, const int* in_sizes, int n_in,
                              void* d_out, int out_size)
{
    const float* nodes = (const float*)d_in[0];
    const float* edges = (const float*)d_in[1];
    const int*   adj   = (const int*)d_in[2];
    const float* Wq    = (const float*)d_in[3];
    const float* bq    = (const float*)d_in[4];
    const float* Wk    = (const float*)d_in[5];
    const float* bk    = (const float*)d_in[6];
    const float* Wv    = (const float*)d_in[7];
    const float* bv    = (const float*)d_in[8];
    const float* We    = (const float*)d_in[9];
    const float* be    = (const float*)d_in[10];
    float* out = (float*)d_out;

    cudaFuncSetAttribute(attn_kernel,
                         cudaFuncAttributeMaxDynamicSharedMemorySize, ESMEM);

    proj_kernel<<<128, 256>>>(nodes, Wq, bq, Wk, bk, Wv, bv, We, be);
    qk_kernel<<<dim3(16, 16, 8), 256>>>();
    attn_kernel<<<512, 512, ESMEM>>>(edges, adj);
    outbias_kernel<<<dim3(16, 8), 256>>>(We, be, out);
    outv_kernel<<<dim3(16, 8, 4), 256>>>(out);
}

// round 5
// speedup vs baseline: 1.1471x; 1.1471x over previous
#include <cuda_runtime.h>
#include <cstdint>

#define NROW 512
#define HH 8
#define DD 32
#define INNER 256
#define ED 64
#define SCALE 0.17677669529663687f  // 1/sqrt(32)
#define ESTRIDE 68                  // padded row stride (floats), conflict-free f4
#define ESMEM (NROW * ESTRIDE * 4)  // 139264 B dynamic smem

// Scratch (device globals; no allocation in kernel_launch).
__device__ float g_q[NROW * INNER];
__device__ float g_k[NROW * INNER];
__device__ float g_v[NROW * INNER];
__device__ float g_t[NROW * HH * ED];      // [i][h][c]  t = We_h^T q_{h,i}
__device__ float g_qbe[NROW * HH];         // q_{h,i} . be_h
__device__ float g_simqk[HH * NROW * NROW];
__device__ float g_attn[HH * NROW * NROW];

typedef unsigned long long ull;

__device__ __forceinline__ ull fma2(ull a, ull b, ull c) {
    ull d;
    asm("fma.rn.f32x2 %0, %1, %2, %3;" : "=l"(d) : "l"(a), "l"(b), "l"(c));
    return d;
}
__device__ __forceinline__ ull add2(ull a, ull b) {
    ull d;
    asm("add.rn.f32x2 %0, %1, %2;" : "=l"(d) : "l"(a), "l"(b));
    return d;
}
__device__ __forceinline__ ull pack2(float lo, float hi) {
    ull d;
    asm("mov.b64 %0, {%1, %2};" : "=l"(d) : "f"(lo), "f"(hi));
    return d;
}
__device__ __forceinline__ float2 unpack2(ull v) {
    float lo, hi;
    asm("mov.b64 {%0, %1}, %2;" : "=f"(lo), "=f"(hi) : "l"(v));
    return make_float2(lo, hi);
}
__device__ __forceinline__ float hsum2(ull v) {
    float2 f = unpack2(v);
    return f.x + f.y;
}
__device__ __forceinline__ void cp16(unsigned int daddr, const void* gptr) {
    asm volatile("cp.async.cg.shared.global [%0], [%1], 16;\n"
                 :: "r"(daddr), "l"(gptr));
}

// ---------------------------------------------------------------------------
// Kernel A: q/k/v projections + t = We_h^T q + qbe.  4 rows per block.
// ---------------------------------------------------------------------------
__global__ __launch_bounds__(256) void proj_kernel(
    const float* __restrict__ nodes,
    const float* __restrict__ Wq, const float* __restrict__ bq,
    const float* __restrict__ Wk, const float* __restrict__ bk,
    const float* __restrict__ Wv, const float* __restrict__ bv,
    const float* __restrict__ We, const float* __restrict__ be)
{
    __shared__ float node_s[4][128];
    __shared__ float q_s[4][INNER];
    const int t = threadIdx.x;
    const int i0 = blockIdx.x * 4;

    for (int idx = t; idx < 4 * 128; idx += 256)
        node_s[idx >> 7][idx & 127] = nodes[i0 * 128 + idx];
    __syncthreads();

    float aq[4], ak[4], av[4];
    const float bqv = bq[t], bkv = bk[t], bvv = bv[t];
#pragma unroll
    for (int r = 0; r < 4; r++) { aq[r] = bqv; ak[r] = bkv; av[r] = bvv; }

#pragma unroll 8
    for (int k = 0; k < 128; k++) {
        const float wq = Wq[k * INNER + t];
        const float wk = Wk[k * INNER + t];
        const float wv = Wv[k * INNER + t];
#pragma unroll
        for (int r = 0; r < 4; r++) {
            const float nv = node_s[r][k];
            aq[r] = fmaf(nv, wq, aq[r]);
            ak[r] = fmaf(nv, wk, ak[r]);
            av[r] = fmaf(nv, wv, av[r]);
        }
    }
#pragma unroll
    for (int r = 0; r < 4; r++) {
        g_q[(i0 + r) * INNER + t] = aq[r];
        g_k[(i0 + r) * INNER + t] = ak[r];
        g_v[(i0 + r) * INNER + t] = av[r];
        q_s[r][t] = aq[r];
    }
    __syncthreads();

    // t[i][h][c] = sum_d We[c, h*32+d] * q[i, h*32+d]
    for (int idx = t; idx < HH * ED; idx += 256) {
        const int h = idx >> 6, c = idx & 63;
        float acc[4] = {0.f, 0.f, 0.f, 0.f};
        const float* wrow = We + c * INNER + h * DD;
#pragma unroll
        for (int d = 0; d < DD; d++) {
            const float w = wrow[d];
#pragma unroll
            for (int r = 0; r < 4; r++)
                acc[r] = fmaf(w, q_s[r][h * DD + d], acc[r]);
        }
#pragma unroll
        for (int r = 0; r < 4; r++)
            g_t[(i0 + r) * (HH * ED) + idx] = acc[r];
    }

    if (t < 4 * HH) {
        const int r = t >> 3, h = t & 7;
        float s = 0.f;
#pragma unroll
        for (int d = 0; d < DD; d++)
            s = fmaf(q_s[r][h * DD + d], be[h * DD + d], s);
        g_qbe[(i0 + r) * HH + h] = s;
    }
}

// ---------------------------------------------------------------------------
// Kernel QK: simqk[h][i][j] = (q_h[i].k_h[j] + qbe[i][h]) * SCALE
// ---------------------------------------------------------------------------
__global__ __launch_bounds__(256) void qk_kernel()
{
    __shared__ float q_s[32][33];
    __shared__ float k_s[32][33];
    const int t = threadIdx.x;
    const int j0 = blockIdx.x * 32;
    const int i0 = blockIdx.y * 32;
    const int h  = blockIdx.z;

    {
        const int r = t >> 3, c4 = (t & 7) * 4;
        const float4 qv = *(const float4*)&g_q[(i0 + r) * INNER + h * DD + c4];
        q_s[r][c4 + 0] = qv.x; q_s[r][c4 + 1] = qv.y;
        q_s[r][c4 + 2] = qv.z; q_s[r][c4 + 3] = qv.w;
        const float4 kv = *(const float4*)&g_k[(j0 + r) * INNER + h * DD + c4];
        k_s[r][c4 + 0] = kv.x; k_s[r][c4 + 1] = kv.y;
        k_s[r][c4 + 2] = kv.z; k_s[r][c4 + 3] = kv.w;
    }
    __syncthreads();

    const int tx = t & 31, ty = t >> 5;
    float acc[4] = {0.f, 0.f, 0.f, 0.f};
#pragma unroll
    for (int d = 0; d < 32; d++) {
        const float kv = k_s[tx][d];
#pragma unroll
        for (int m = 0; m < 4; m++)
            acc[m] = fmaf(q_s[ty + m * 8][d], kv, acc[m]);
    }
#pragma unroll
    for (int m = 0; m < 4; m++) {
        const int i = i0 + ty + m * 8;
        g_simqk[((size_t)h * NROW + i) * NROW + j0 + tx] =
            (acc[m] + g_qbe[i * HH + h]) * SCALE;
    }
}

// ---------------------------------------------------------------------------
// Kernel B: per node-row i — edge scores + softmax + edge aggregation +
// edge-output epilogue (out = agg @ We + rowsum*be). One block per row.
// ---------------------------------------------------------------------------
__global__ __launch_bounds__(512) void attn_kernel(
    const float* __restrict__ edges, const int* __restrict__ adj,
    const float* __restrict__ We, const float* __restrict__ be,
    float* __restrict__ out)
{
    extern __shared__ __align__(16) float e_s[];       // [512][ESTRIDE]
    __shared__ __align__(16) float t_s[HH * ESTRIDE];  // t, padded
    __shared__ float sim_s[HH * NROW];                 // simqk -> sim -> attn
    __shared__ __align__(16) float agg_s[HH * ESTRIDE];
    __shared__ float rs_s[HH];
    __shared__ int   adj_s[NROW];

    const int t = threadIdx.x;
    const int i = blockIdx.x;

    // ---- issue cp.async for the whole edge row (one commit group) ----
    {
        const float* gsrc = edges + (size_t)i * NROW * ED;
        unsigned int sbase = (unsigned int)__cvta_generic_to_shared(e_s);
#pragma unroll
        for (int it = 0; it < 16; it++) {
            const int idx = t + it * 512;             // 8192 float4s
            const int row = idx >> 4, c4 = idx & 15;
            cp16(sbase + (unsigned int)(row * ESTRIDE + c4 * 4) * 4,
                 gsrc + (size_t)row * ED + c4 * 4);
        }
        asm volatile("cp.async.commit_group;\n" ::: "memory");
    }

    // ---- overlap DMA with staging t, simqk, adj ----
    t_s[(t >> 6) * ESTRIDE + (t & 63)] = g_t[i * (HH * ED) + t];
    adj_s[t] = adj[i * NROW + t];
#pragma unroll
    for (int k = 0; k < 8; k++) {
        const int idx = t + k * 512;                  // h = idx>>9, j = idx&511
        sim_s[idx] = g_simqk[((size_t)(idx >> 9) * NROW + i) * NROW + (idx & 511)];
    }
    asm volatile("cp.async.wait_group 0;\n" ::: "memory");
    __syncthreads();

    // ---- pass 1: sim[h][j] = (edges_ij . t[h]) * SCALE + simqk ----
    {
        const int j = t;
        ull acc[HH];
#pragma unroll
        for (int h = 0; h < HH; h++) acc[h] = 0ull;
        const longlong2* ep = (const longlong2*)&e_s[j * ESTRIDE];
#pragma unroll
        for (int c4 = 0; c4 < 16; c4++) {
            const longlong2 e2 = ep[c4];
#pragma unroll
            for (int h = 0; h < HH; h++) {
                const longlong2 t2 = *(const longlong2*)&t_s[h * ESTRIDE + c4 * 4];
                acc[h] = fma2((ull)e2.x, (ull)t2.x, acc[h]);
                acc[h] = fma2((ull)e2.y, (ull)t2.y, acc[h]);
            }
        }
#pragma unroll
        for (int h = 0; h < HH; h++)
            sim_s[h * NROW + j] = fmaf(hsum2(acc[h]), SCALE, sim_s[h * NROW + j]);
    }
    __syncthreads();

    // ---- softmax (row-constant mean shift cancels exactly) ----
    {
        const int w = t >> 5, lane = t & 31;          // warps 0..7 = heads
        if (w < HH) {
            float part = 0.f;
#pragma unroll
            for (int k = 0; k < 16; k++) {
                const int j = lane + k * 32;
                const float s = sim_s[w * NROW + j];
                const float ex = adj_s[j] ? __expf(s) : 0.f;
                sim_s[w * NROW + j] = ex;
                part += ex;
            }
#pragma unroll
            for (int o = 16; o > 0; o >>= 1)
                part += __shfl_xor_sync(0xffffffffu, part, o);
            const float inv = part > 0.f ? 1.f / part : 0.f;
            if (lane == 0) rs_s[w] = part > 0.f ? 1.f : 0.f;
#pragma unroll
            for (int k = 0; k < 16; k++) {
                const int j = lane + k * 32;
                const float a = sim_s[w * NROW + j] * inv;
                sim_s[w * NROW + j] = a;
                g_attn[((size_t)w * NROW + i) * NROW + j] = a;
            }
        }
    }
    __syncthreads();

    // ---- pass 2: agg[h][c] = sum_j attn[h][j] * edges[i][j][c] ----
    {
        const int c4w = t >> 5;   // 0..15 (c-quad)
        const int l   = t & 31;   // j offset
        ull accA[HH], accB[HH];
#pragma unroll
        for (int h = 0; h < HH; h++) { accA[h] = 0ull; accB[h] = 0ull; }
#pragma unroll 4
        for (int kk = 0; kk < 16; kk++) {
            const int j = l + kk * 32;
            const longlong2 e2 = *(const longlong2*)&e_s[j * ESTRIDE + c4w * 4];
#pragma unroll
            for (int h = 0; h < HH; h++) {
                const float a = sim_s[h * NROW + j];
                const ull aa = pack2(a, a);
                accA[h] = fma2(aa, (ull)e2.x, accA[h]);
                accB[h] = fma2(aa, (ull)e2.y, accB[h]);
            }
        }
#pragma unroll
        for (int o = 16; o > 0; o >>= 1) {
#pragma unroll
            for (int h = 0; h < HH; h++) {
                accA[h] = add2(accA[h], __shfl_xor_sync(0xffffffffu, accA[h], o));
                accB[h] = add2(accB[h], __shfl_xor_sync(0xffffffffu, accB[h], o));
            }
        }
        if (l == 0) {
#pragma unroll
            for (int h = 0; h < HH; h++) {
                const float2 a = unpack2(accA[h]);
                const float2 b = unpack2(accB[h]);
                agg_s[h * ESTRIDE + c4w * 4 + 0] = a.x;
                agg_s[h * ESTRIDE + c4w * 4 + 1] = a.y;
                agg_s[h * ESTRIDE + c4w * 4 + 2] = b.x;
                agg_s[h * ESTRIDE + c4w * 4 + 3] = b.y;
            }
        }
    }
    __syncthreads();

    // ---- epilogue: out[i, h*32+d] = agg[h]·We[:, h*32+d] + rowsum*be ----
    if (t < 256) {
        const int h = t >> 5, d = t & 31;
        float acc = rs_s[h] * be[h * DD + d];
#pragma unroll 8
        for (int c = 0; c < ED; c++)
            acc = fmaf(agg_s[h * ESTRIDE + c], We[c * INNER + h * DD + d], acc);
        out[i * INNER + h * DD + d] = acc;
    }
}

// ---------------------------------------------------------------------------
// Kernel C: out += attn @ v, j split 4-ways, atomicAdd epilogue.
// f32x2 over j-pairs; v tile transposed with 8-byte-aligned stride VPAD=130
// (130 mod 32 = 2 -> each 16-lane phase hits distinct bank pairs).
// ---------------------------------------------------------------------------
#define VPAD 130
__global__ __launch_bounds__(256) void outv_kernel(float* __restrict__ out)
{
    __shared__ float a_s[32 * 128];                   // attn tile [i-local][j-local]
    __shared__ __align__(8) float v_sT[32 * VPAD];    // v transposed [d][j-local]
    const int t = threadIdx.x;
    const int i0 = blockIdx.x * 32;
    const int h  = blockIdx.y;
    const int j0 = blockIdx.z * 128;

#pragma unroll
    for (int f = 0; f < 4; f++) {
        const int idx = t + f * 256;          // 1024 float4s attn 32x128
        const int row = idx >> 5, c4 = idx & 31;
        *(float4*)&a_s[row * 128 + c4 * 4] =
            *(const float4*)&g_attn[((size_t)h * NROW + i0 + row) * NROW + j0 + c4 * 4];
    }
#pragma unroll
    for (int f = 0; f < 4; f++) {
        const int idx = t + f * 256;          // 1024 float4s v 128x32 (transpose)
        const int row = idx >> 3, c4 = idx & 7;
        const float4 v4 = *(const float4*)&g_v[(j0 + row) * INNER + h * DD + c4 * 4];
        v_sT[(c4 * 4 + 0) * VPAD + row] = v4.x;
        v_sT[(c4 * 4 + 1) * VPAD + row] = v4.y;
        v_sT[(c4 * 4 + 2) * VPAD + row] = v4.z;
        v_sT[(c4 * 4 + 3) * VPAD + row] = v4.w;
    }
    __syncthreads();

    const int d  = t & 31;
    const int i4 = t >> 5;
    ull acc[4] = {0ull, 0ull, 0ull, 0ull};
#pragma unroll 8
    for (int jp = 0; jp < 64; jp++) {
        const ull v2 = *(const ull*)&v_sT[d * VPAD + jp * 2];
#pragma unroll
        for (int m = 0; m < 4; m++) {
            const ull av2 = *(const ull*)&a_s[(i4 + m * 8) * 128 + jp * 2];
            acc[m] = fma2(av2, v2, acc[m]);
        }
    }
#pragma unroll
    for (int m = 0; m < 4; m++)
        atomicAdd(&out[(i0 + i4 + m * 8) * INNER + h * DD + d], hsum2(acc[m]));
}

// ---------------------------------------------------------------------------
extern "C" void kernel_launch(void* const* d_in, const int* in_sizes, int n_in,
                              void* d_out, int out_size)
{
    const float* nodes = (const float*)d_in[0];
    const float* edges = (const float*)d_in[1];
    const int*   adj   = (const int*)d_in[2];
    const float* Wq    = (const float*)d_in[3];
    const float* bq    = (const float*)d_in[4];
    const float* Wk    = (const float*)d_in[5];
    const float* bk    = (const float*)d_in[6];
    const float* Wv    = (const float*)d_in[7];
    const float* bv    = (const float*)d_in[8];
    const float* We    = (const float*)d_in[9];
    const float* be    = (const float*)d_in[10];
    float* out = (float*)d_out;

    cudaFuncSetAttribute(attn_kernel,
                         cudaFuncAttributeMaxDynamicSharedMemorySize, ESMEM);

    proj_kernel<<<128, 256>>>(nodes, Wq, bq, Wk, bk, Wv, bv, We, be);
    qk_kernel<<<dim3(16, 16, 8), 256>>>();
    attn_kernel<<<512, 512, ESMEM>>>(edges, adj, We, be, out);
    outv_kernel<<<dim3(16, 8, 4), 256>>>(out);
}

// round 6
// speedup vs baseline: 1.1947x; 1.0415x over previous
#include <cuda_runtime.h>
#include <cstdint>

#define NROW 512
#define HH 8
#define DD 32
#define INNER 256
#define ED 64
#define SCALE 0.17677669529663687f  // 1/sqrt(32)
#define ESTRIDE 68                  // padded row stride (floats), conflict-free f4
#define HSMEM (256 * ESTRIDE * 4)   // 69632 B dynamic smem (half row)

// Scratch (device globals; no allocation in kernel_launch).
__device__ float g_q[NROW * INNER];
__device__ float g_k[NROW * INNER];
__device__ float g_v[NROW * INNER];
__device__ float g_t[NROW * HH * ED];        // [i][h][c]  t = We_h^T q_{h,i}
__device__ float g_qbe[NROW * HH];           // q_{h,i} . be_h
__device__ float g_simqk[HH * NROW * NROW];
__device__ float g_esim[HH * NROW * NROW];   // unnormalized exp*adj
__device__ float g_aggu[2 * NROW * HH * ED]; // [half][i][h][c] partial agg
__device__ float g_sump[2 * HH * NROW];      // [half][h][i] partial sums
__device__ float g_inv[HH * NROW];           // 1/sum or 0

typedef unsigned long long ull;

__device__ __forceinline__ ull fma2(ull a, ull b, ull c) {
    ull d;
    asm("fma.rn.f32x2 %0, %1, %2, %3;" : "=l"(d) : "l"(a), "l"(b), "l"(c));
    return d;
}
__device__ __forceinline__ ull add2(ull a, ull b) {
    ull d;
    asm("add.rn.f32x2 %0, %1, %2;" : "=l"(d) : "l"(a), "l"(b));
    return d;
}
__device__ __forceinline__ ull pack2(float lo, float hi) {
    ull d;
    asm("mov.b64 %0, {%1, %2};" : "=l"(d) : "f"(lo), "f"(hi));
    return d;
}
__device__ __forceinline__ float2 unpack2(ull v) {
    float lo, hi;
    asm("mov.b64 {%0, %1}, %2;" : "=f"(lo), "=f"(hi) : "l"(v));
    return make_float2(lo, hi);
}
__device__ __forceinline__ float hsum2(ull v) {
    float2 f = unpack2(v);
    return f.x + f.y;
}
__device__ __forceinline__ void cp16(unsigned int daddr, const void* gptr) {
    asm volatile("cp.async.cg.shared.global [%0], [%1], 16;\n"
                 :: "r"(daddr), "l"(gptr));
}

// ---------------------------------------------------------------------------
// Kernel A: q/k/v projections + t = We_h^T q + qbe.  4 rows per block.
// ---------------------------------------------------------------------------
__global__ __launch_bounds__(256) void proj_kernel(
    const float* __restrict__ nodes,
    const float* __restrict__ Wq, const float* __restrict__ bq,
    const float* __restrict__ Wk, const float* __restrict__ bk,
    const float* __restrict__ Wv, const float* __restrict__ bv,
    const float* __restrict__ We, const float* __restrict__ be)
{
    __shared__ float node_s[4][128];
    __shared__ float q_s[4][INNER];
    const int t = threadIdx.x;
    const int i0 = blockIdx.x * 4;

    for (int idx = t; idx < 4 * 128; idx += 256)
        node_s[idx >> 7][idx & 127] = nodes[i0 * 128 + idx];
    __syncthreads();

    float aq[4], ak[4], av[4];
    const float bqv = bq[t], bkv = bk[t], bvv = bv[t];
#pragma unroll
    for (int r = 0; r < 4; r++) { aq[r] = bqv; ak[r] = bkv; av[r] = bvv; }

#pragma unroll 8
    for (int k = 0; k < 128; k++) {
        const float wq = Wq[k * INNER + t];
        const float wk = Wk[k * INNER + t];
        const float wv = Wv[k * INNER + t];
#pragma unroll
        for (int r = 0; r < 4; r++) {
            const float nv = node_s[r][k];
            aq[r] = fmaf(nv, wq, aq[r]);
            ak[r] = fmaf(nv, wk, ak[r]);
            av[r] = fmaf(nv, wv, av[r]);
        }
    }
#pragma unroll
    for (int r = 0; r < 4; r++) {
        g_q[(i0 + r) * INNER + t] = aq[r];
        g_k[(i0 + r) * INNER + t] = ak[r];
        g_v[(i0 + r) * INNER + t] = av[r];
        q_s[r][t] = aq[r];
    }
    __syncthreads();

    // t[i][h][c] = sum_d We[c, h*32+d] * q[i, h*32+d]
    for (int idx = t; idx < HH * ED; idx += 256) {
        const int h = idx >> 6, c = idx & 63;
        float acc[4] = {0.f, 0.f, 0.f, 0.f};
        const float* wrow = We + c * INNER + h * DD;
#pragma unroll
        for (int d = 0; d < DD; d++) {
            const float w = wrow[d];
#pragma unroll
            for (int r = 0; r < 4; r++)
                acc[r] = fmaf(w, q_s[r][h * DD + d], acc[r]);
        }
#pragma unroll
        for (int r = 0; r < 4; r++)
            g_t[(i0 + r) * (HH * ED) + idx] = acc[r];
    }

    if (t < 4 * HH) {
        const int r = t >> 3, h = t & 7;
        float s = 0.f;
#pragma unroll
        for (int d = 0; d < DD; d++)
            s = fmaf(q_s[r][h * DD + d], be[h * DD + d], s);
        g_qbe[(i0 + r) * HH + h] = s;
    }
}

// ---------------------------------------------------------------------------
// Kernel QK: simqk[h][i][j] = (q_h[i].k_h[j] + qbe[i][h]) * SCALE
// ---------------------------------------------------------------------------
__global__ __launch_bounds__(256) void qk_kernel()
{
    __shared__ float q_s[32][33];
    __shared__ float k_s[32][33];
    const int t = threadIdx.x;
    const int j0 = blockIdx.x * 32;
    const int i0 = blockIdx.y * 32;
    const int h  = blockIdx.z;

    {
        const int r = t >> 3, c4 = (t & 7) * 4;
        const float4 qv = *(const float4*)&g_q[(i0 + r) * INNER + h * DD + c4];
        q_s[r][c4 + 0] = qv.x; q_s[r][c4 + 1] = qv.y;
        q_s[r][c4 + 2] = qv.z; q_s[r][c4 + 3] = qv.w;
        const float4 kv = *(const float4*)&g_k[(j0 + r) * INNER + h * DD + c4];
        k_s[r][c4 + 0] = kv.x; k_s[r][c4 + 1] = kv.y;
        k_s[r][c4 + 2] = kv.z; k_s[r][c4 + 3] = kv.w;
    }
    __syncthreads();

    const int tx = t & 31, ty = t >> 5;
    float acc[4] = {0.f, 0.f, 0.f, 0.f};
#pragma unroll
    for (int d = 0; d < 32; d++) {
        const float kv = k_s[tx][d];
#pragma unroll
        for (int m = 0; m < 4; m++)
            acc[m] = fmaf(q_s[ty + m * 8][d], kv, acc[m]);
    }
#pragma unroll
    for (int m = 0; m < 4; m++) {
        const int i = i0 + ty + m * 8;
        g_simqk[((size_t)h * NROW + i) * NROW + j0 + tx] =
            (acc[m] + g_qbe[i * HH + h]) * SCALE;
    }
}

// ---------------------------------------------------------------------------
// Kernel B1: half-row sim + exp + partial sums + partial unnormalized agg.
// grid 1024 = (row i) x (half). 256 threads, 64 KB edges in smem -> occ 2.
// Normalization is linear, so halves are fully independent (no atomics).
// ---------------------------------------------------------------------------
__global__ __launch_bounds__(256) void simagg_kernel(
    const float* __restrict__ edges, const int* __restrict__ adj)
{
    extern __shared__ __align__(16) float e_s[];       // [256][ESTRIDE]
    __shared__ __align__(16) float t_s[HH * ESTRIDE];
    __shared__ float sim_s[HH * 256];                  // esim values
    __shared__ int   adj_s[256];
    __shared__ float wsum[8 * 8];                      // [warp][h]

    const int t = threadIdx.x;
    const int i = blockIdx.x >> 1;
    const int half = blockIdx.x & 1;
    const int jbase = half * 256;

    // ---- DMA 64 KB: edges[i, jbase..jbase+256, :] ----
    {
        const float* gsrc = edges + ((size_t)i * NROW + jbase) * ED;
        unsigned int sbase = (unsigned int)__cvta_generic_to_shared(e_s);
#pragma unroll
        for (int it = 0; it < 16; it++) {
            const int idx = t + it * 256;             // 4096 float4s
            const int row = idx >> 4, c4 = idx & 15;
            cp16(sbase + (unsigned int)(row * ESTRIDE + c4 * 4) * 4,
                 gsrc + (size_t)row * ED + c4 * 4);
        }
        asm volatile("cp.async.commit_group;\n" ::: "memory");
    }

    // ---- overlap DMA with staging (t in smem, simqk in regs per thread=j) ----
#pragma unroll
    for (int k = 0; k < 2; k++) {
        const int idx = t + k * 256;
        t_s[(idx >> 6) * ESTRIDE + (idx & 63)] = g_t[i * (HH * ED) + idx];
    }
    adj_s[t] = adj[i * NROW + jbase + t];
    float sq[HH];
#pragma unroll
    for (int h = 0; h < HH; h++)
        sq[h] = g_simqk[((size_t)h * NROW + i) * NROW + jbase + t];

    asm volatile("cp.async.wait_group 0;\n" ::: "memory");
    __syncthreads();

    // ---- pass 1: edge row in registers; 8 head dots; fused exp ----
    const int j = t;
    float ex[HH];
    {
        ull er[32];
        const longlong2* ep = (const longlong2*)&e_s[j * ESTRIDE];
#pragma unroll
        for (int c4 = 0; c4 < 16; c4++) {
            const longlong2 q = ep[c4];
            er[2 * c4]     = (ull)q.x;
            er[2 * c4 + 1] = (ull)q.y;
        }
        const int av = adj_s[j];
#pragma unroll
        for (int h = 0; h < HH; h++) {
            ull acc = 0ull;
            const ull* tp = (const ull*)&t_s[h * ESTRIDE];
#pragma unroll
            for (int c = 0; c < 32; c++)
                acc = fma2(er[c], tp[c], acc);
            const float simv = fmaf(hsum2(acc), SCALE, sq[h]);
            ex[h] = av ? __expf(simv) : 0.f;
        }
    }

    // store esim (smem + gmem) and reduce partial sums
#pragma unroll
    for (int h = 0; h < HH; h++) {
        sim_s[h * 256 + j] = ex[h];
        g_esim[((size_t)h * NROW + i) * NROW + jbase + j] = ex[h];
    }
    {
        float s[HH];
#pragma unroll
        for (int h = 0; h < HH; h++) s[h] = ex[h];
#pragma unroll
        for (int o = 16; o > 0; o >>= 1)
#pragma unroll
            for (int h = 0; h < HH; h++)
                s[h] += __shfl_xor_sync(0xffffffffu, s[h], o);
        if ((t & 31) == 0) {
            const int w = t >> 5;
#pragma unroll
            for (int h = 0; h < HH; h++) wsum[w * 8 + h] = s[h];
        }
    }
    __syncthreads();
    if (t < HH) {
        float s = 0.f;
#pragma unroll
        for (int w = 0; w < 8; w++) s += wsum[w * 8 + t];
        g_sump[half * (HH * NROW) + t * NROW + i] = s;
    }

    // ---- pass 2: aggu[h][c] = sum_j esim[h][j] * e[j][c] ----
    {
        const int w = t >> 5;     // warp: c4 in {w, w+8}
        const int l = t & 31;     // j offset
        ull aA[2][HH], aB[2][HH];
#pragma unroll
        for (int p = 0; p < 2; p++)
#pragma unroll
            for (int h = 0; h < HH; h++) { aA[p][h] = 0ull; aB[p][h] = 0ull; }

#pragma unroll 2
        for (int kk = 0; kk < 8; kk++) {
            const int jj = l + kk * 32;
            ull ap[HH];
#pragma unroll
            for (int h = 0; h < HH; h++) {
                const float a = sim_s[h * 256 + jj];
                ap[h] = pack2(a, a);
            }
#pragma unroll
            for (int p = 0; p < 2; p++) {
                const int c4 = w + p * 8;
                const longlong2 e2 = *(const longlong2*)&e_s[jj * ESTRIDE + c4 * 4];
#pragma unroll
                for (int h = 0; h < HH; h++) {
                    aA[p][h] = fma2(ap[h], (ull)e2.x, aA[p][h]);
                    aB[p][h] = fma2(ap[h], (ull)e2.y, aB[p][h]);
                }
            }
        }
#pragma unroll
        for (int o = 16; o > 0; o >>= 1)
#pragma unroll
            for (int p = 0; p < 2; p++)
#pragma unroll
                for (int h = 0; h < HH; h++) {
                    aA[p][h] = add2(aA[p][h], __shfl_xor_sync(0xffffffffu, aA[p][h], o));
                    aB[p][h] = add2(aB[p][h], __shfl_xor_sync(0xffffffffu, aB[p][h], o));
                }
        if (l == 0) {
            float* dst = &g_aggu[((size_t)(half * NROW + i) * HH) * ED];
#pragma unroll
            for (int p = 0; p < 2; p++) {
                const int c4 = w + p * 8;
#pragma unroll
                for (int h = 0; h < HH; h++) {
                    const float2 a = unpack2(aA[p][h]);
                    const float2 b = unpack2(aB[p][h]);
                    *(float4*)&dst[h * ED + c4 * 4] = make_float4(a.x, a.y, b.x, b.y);
                }
            }
        }
    }
}

// ---------------------------------------------------------------------------
// Kernel B2: combine halves; out = (aggu*inv) @ We + rs*be; emit g_inv.
// grid (64 i-tiles of 8, 8 heads) = 512 blocks, 256 threads, all-smem FMA.
// ---------------------------------------------------------------------------
__global__ __launch_bounds__(256) void finish_kernel(
    const float* __restrict__ We, const float* __restrict__ be,
    float* __restrict__ out)
{
    __shared__ float we_s[ED * DD];     // [c][d] 8 KB
    __shared__ float agg_s[8 * ED];     // [r][c] 2 KB
    __shared__ float inv_s[8], rs_s[8];

    const int t = threadIdx.x;
    const int i0 = blockIdx.x * 8;
    const int h  = blockIdx.y;
    const int d  = t & 31;
    const int r  = t >> 5;

#pragma unroll
    for (int k = 0; k < 8; k++) {
        const int idx = t + k * 256;    // c = idx>>5, dd = idx&31
        we_s[idx] = We[(idx >> 5) * INNER + h * DD + (idx & 31)];
    }
#pragma unroll
    for (int k = 0; k < 2; k++) {
        const int idx = t + k * 256;    // rr = idx>>6, c = idx&63
        const int rr = idx >> 6, c = idx & 63;
        agg_s[idx] = g_aggu[((size_t)(i0 + rr) * HH + h) * ED + c]
                   + g_aggu[((size_t)(NROW + i0 + rr) * HH + h) * ED + c];
    }
    if (t < 8) {
        const float s = g_sump[h * NROW + i0 + t]
                      + g_sump[HH * NROW + h * NROW + i0 + t];
        const float inv = s > 0.f ? 1.f / s : 0.f;
        inv_s[t] = inv;
        rs_s[t]  = s > 0.f ? 1.f : 0.f;
        g_inv[h * NROW + i0 + t] = inv;
    }
    __syncthreads();

    float acc = 0.f;
#pragma unroll 8
    for (int c = 0; c < ED; c++)
        acc = fmaf(agg_s[r * ED + c], we_s[c * DD + d], acc);
    out[(i0 + r) * INNER + h * DD + d] =
        fmaf(rs_s[r], be[h * DD + d], acc * inv_s[r]);
}

// ---------------------------------------------------------------------------
// Kernel C: out += (esim*inv) @ v, j split 4-ways, atomicAdd epilogue.
// ---------------------------------------------------------------------------
#define VPAD 130
__global__ __launch_bounds__(256) void outv_kernel(float* __restrict__ out)
{
    __shared__ float a_s[32 * 128];                   // esim tile [i-local][j-local]
    __shared__ __align__(8) float v_sT[32 * VPAD];    // v transposed [d][j-local]
    __shared__ float inv_s[32];
    const int t = threadIdx.x;
    const int i0 = blockIdx.x * 32;
    const int h  = blockIdx.y;
    const int j0 = blockIdx.z * 128;

    if (t < 32) inv_s[t] = g_inv[h * NROW + i0 + t];
#pragma unroll
    for (int f = 0; f < 4; f++) {
        const int idx = t + f * 256;          // 1024 float4s esim 32x128
        const int row = idx >> 5, c4 = idx & 31;
        *(float4*)&a_s[row * 128 + c4 * 4] =
            *(const float4*)&g_esim[((size_t)h * NROW + i0 + row) * NROW + j0 + c4 * 4];
    }
#pragma unroll
    for (int f = 0; f < 4; f++) {
        const int idx = t + f * 256;          // 1024 float4s v 128x32 (transpose)
        const int row = idx >> 3, c4 = idx & 7;
        const float4 v4 = *(const float4*)&g_v[(j0 + row) * INNER + h * DD + c4 * 4];
        v_sT[(c4 * 4 + 0) * VPAD + row] = v4.x;
        v_sT[(c4 * 4 + 1) * VPAD + row] = v4.y;
        v_sT[(c4 * 4 + 2) * VPAD + row] = v4.z;
        v_sT[(c4 * 4 + 3) * VPAD + row] = v4.w;
    }
    __syncthreads();

    const int d  = t & 31;
    const int i4 = t >> 5;
    ull acc[4] = {0ull, 0ull, 0ull, 0ull};
#pragma unroll 8
    for (int jp = 0; jp < 64; jp++) {
        const ull v2 = *(const ull*)&v_sT[d * VPAD + jp * 2];
#pragma unroll
        for (int m = 0; m < 4; m++) {
            const ull av2 = *(const ull*)&a_s[(i4 + m * 8) * 128 + jp * 2];
            acc[m] = fma2(av2, v2, acc[m]);
        }
    }
#pragma unroll
    for (int m = 0; m < 4; m++)
        atomicAdd(&out[(i0 + i4 + m * 8) * INNER + h * DD + d],
                  hsum2(acc[m]) * inv_s[i4 + m * 8]);
}

// ---------------------------------------------------------------------------
extern "C" void kernel_launch(void* const* d_in, const int* in_sizes, int n_in,
                              void* d_out, int out_size)
{
    const float* nodes = (const float*)d_in[0];
    const float* edges = (const float*)d_in[1];
    const int*   adj   = (const int*)d_in[2];
    const float* Wq    = (const float*)d_in[3];
    const float* bq    = (const float*)d_in[4];
    const float* Wk    = (const float*)d_in[5];
    const float* bk    = (const float*)d_in[6];
    const float* Wv    = (const float*)d_in[7];
    const float* bv    = (const float*)d_in[8];
    const float* We    = (const float*)d_in[9];
    const float* be    = (const float*)d_in[10];
    float* out = (float*)d_out;

    cudaFuncSetAttribute(simagg_kernel,
                         cudaFuncAttributeMaxDynamicSharedMemorySize, HSMEM);

    proj_kernel<<<128, 256>>>(nodes, Wq, bq, Wk, bk, Wv, bv, We, be);
    qk_kernel<<<dim3(16, 16, 8), 256>>>();
    simagg_kernel<<<1024, 256, HSMEM>>>(edges, adj);
    finish_kernel<<<dim3(64, 8), 256>>>(We, be, out);
    outv_kernel<<<dim3(16, 8, 4), 256>>>(out);
}

// round 7
// speedup vs baseline: 1.2262x; 1.0264x over previous
#include <cuda_runtime.h>
#include <cstdint>

#define NROW 512
#define HH 8
#define DD 32
#define INNER 256
#define ED 64
#define SCALE 0.17677669529663687f  // 1/sqrt(32)
#define ESTRIDE 68                  // padded row stride (floats), conflict-free f4
#define HSMEM (256 * ESTRIDE * 4)   // 69632 B dynamic smem (half row)

// Scratch (device globals; no allocation in kernel_launch).
__device__ float g_q[NROW * INNER];
__device__ float g_k[NROW * INNER];
__device__ float g_v[NROW * INNER];
__device__ float g_t[NROW * HH * ED];        // [i][h][c]  t = We_h^T q_{h,i}
__device__ float g_qbe[NROW * HH];           // q_{h,i} . be_h
__device__ float g_simqk[HH * NROW * NROW];
__device__ float g_esim[HH * NROW * NROW];   // unnormalized exp*adj
__device__ float g_aggu[2 * NROW * HH * ED]; // [half][i][h][c] partial agg
__device__ float g_sump[2 * HH * NROW];      // [half][h][i] partial sums
__device__ float g_inv[HH * NROW];           // 1/sum or 0

typedef unsigned long long ull;

__device__ __forceinline__ ull fma2(ull a, ull b, ull c) {
    ull d;
    asm("fma.rn.f32x2 %0, %1, %2, %3;" : "=l"(d) : "l"(a), "l"(b), "l"(c));
    return d;
}
__device__ __forceinline__ ull add2(ull a, ull b) {
    ull d;
    asm("add.rn.f32x2 %0, %1, %2;" : "=l"(d) : "l"(a), "l"(b));
    return d;
}
__device__ __forceinline__ ull pack2(float lo, float hi) {
    ull d;
    asm("mov.b64 %0, {%1, %2};" : "=l"(d) : "f"(lo), "f"(hi));
    return d;
}
__device__ __forceinline__ float2 unpack2(ull v) {
    float lo, hi;
    asm("mov.b64 {%0, %1}, %2;" : "=f"(lo), "=f"(hi) : "l"(v));
    return make_float2(lo, hi);
}
__device__ __forceinline__ float hsum2(ull v) {
    float2 f = unpack2(v);
    return f.x + f.y;
}
__device__ __forceinline__ void cp16(unsigned int daddr, const void* gptr) {
    asm volatile("cp.async.cg.shared.global [%0], [%1], 16;\n"
                 :: "r"(daddr), "l"(gptr));
}

// ---------------------------------------------------------------------------
// Kernel A: q/k/v projections + t = We_h^T q + qbe.  4 rows per block.
// ---------------------------------------------------------------------------
__global__ __launch_bounds__(256) void proj_kernel(
    const float* __restrict__ nodes,
    const float* __restrict__ Wq, const float* __restrict__ bq,
    const float* __restrict__ Wk, const float* __restrict__ bk,
    const float* __restrict__ Wv, const float* __restrict__ bv,
    const float* __restrict__ We, const float* __restrict__ be)
{
    __shared__ float node_s[4][128];
    __shared__ float q_s[4][INNER];
    const int t = threadIdx.x;
    const int i0 = blockIdx.x * 4;

    for (int idx = t; idx < 4 * 128; idx += 256)
        node_s[idx >> 7][idx & 127] = nodes[i0 * 128 + idx];
    __syncthreads();

    float aq[4], ak[4], av[4];
    const float bqv = bq[t], bkv = bk[t], bvv = bv[t];
#pragma unroll
    for (int r = 0; r < 4; r++) { aq[r] = bqv; ak[r] = bkv; av[r] = bvv; }

#pragma unroll 8
    for (int k = 0; k < 128; k++) {
        const float wq = Wq[k * INNER + t];
        const float wk = Wk[k * INNER + t];
        const float wv = Wv[k * INNER + t];
#pragma unroll
        for (int r = 0; r < 4; r++) {
            const float nv = node_s[r][k];
            aq[r] = fmaf(nv, wq, aq[r]);
            ak[r] = fmaf(nv, wk, ak[r]);
            av[r] = fmaf(nv, wv, av[r]);
        }
    }
#pragma unroll
    for (int r = 0; r < 4; r++) {
        g_q[(i0 + r) * INNER + t] = aq[r];
        g_k[(i0 + r) * INNER + t] = ak[r];
        g_v[(i0 + r) * INNER + t] = av[r];
        q_s[r][t] = aq[r];
    }
    __syncthreads();

    // t[i][h][c] = sum_d We[c, h*32+d] * q[i, h*32+d]
    for (int idx = t; idx < HH * ED; idx += 256) {
        const int h = idx >> 6, c = idx & 63;
        float acc[4] = {0.f, 0.f, 0.f, 0.f};
        const float* wrow = We + c * INNER + h * DD;
#pragma unroll
        for (int d = 0; d < DD; d++) {
            const float w = wrow[d];
#pragma unroll
            for (int r = 0; r < 4; r++)
                acc[r] = fmaf(w, q_s[r][h * DD + d], acc[r]);
        }
#pragma unroll
        for (int r = 0; r < 4; r++)
            g_t[(i0 + r) * (HH * ED) + idx] = acc[r];
    }

    if (t < 4 * HH) {
        const int r = t >> 3, h = t & 7;
        float s = 0.f;
#pragma unroll
        for (int d = 0; d < DD; d++)
            s = fmaf(q_s[r][h * DD + d], be[h * DD + d], s);
        g_qbe[(i0 + r) * HH + h] = s;
    }
}

// ---------------------------------------------------------------------------
// Kernel QK: simqk[h][i][j] = (q_h[i].k_h[j] + qbe[i][h]) * SCALE
// ---------------------------------------------------------------------------
__global__ __launch_bounds__(256) void qk_kernel()
{
    __shared__ float q_s[32][33];
    __shared__ float k_s[32][33];
    const int t = threadIdx.x;
    const int j0 = blockIdx.x * 32;
    const int i0 = blockIdx.y * 32;
    const int h  = blockIdx.z;

    {
        const int r = t >> 3, c4 = (t & 7) * 4;
        const float4 qv = *(const float4*)&g_q[(i0 + r) * INNER + h * DD + c4];
        q_s[r][c4 + 0] = qv.x; q_s[r][c4 + 1] = qv.y;
        q_s[r][c4 + 2] = qv.z; q_s[r][c4 + 3] = qv.w;
        const float4 kv = *(const float4*)&g_k[(j0 + r) * INNER + h * DD + c4];
        k_s[r][c4 + 0] = kv.x; k_s[r][c4 + 1] = kv.y;
        k_s[r][c4 + 2] = kv.z; k_s[r][c4 + 3] = kv.w;
    }
    __syncthreads();

    const int tx = t & 31, ty = t >> 5;
    float acc[4] = {0.f, 0.f, 0.f, 0.f};
#pragma unroll
    for (int d = 0; d < 32; d++) {
        const float kv = k_s[tx][d];
#pragma unroll
        for (int m = 0; m < 4; m++)
            acc[m] = fmaf(q_s[ty + m * 8][d], kv, acc[m]);
    }
#pragma unroll
    for (int m = 0; m < 4; m++) {
        const int i = i0 + ty + m * 8;
        g_simqk[((size_t)h * NROW + i) * NROW + j0 + tx] =
            (acc[m] + g_qbe[i * HH + h]) * SCALE;
    }
}

// ---------------------------------------------------------------------------
// Kernel B1: half-row sim + exp + partial sums + partial unnormalized agg.
// grid 1024 = (row i) x (half). 256 threads, occ 2 forced via launch_bounds.
// Pass 2 has NO cross-lane reduction: thread owns (jgroup, h, c4).
// ---------------------------------------------------------------------------
__global__ __launch_bounds__(256, 2) void simagg_kernel(
    const float* __restrict__ edges, const int* __restrict__ adj)
{
    extern __shared__ __align__(16) float e_s[];       // [256][ESTRIDE]
    __shared__ __align__(16) float t_s[HH * ESTRIDE];
    __shared__ ull sim_d[256 * 9];                     // [j][h] dup-packed, stride 9
    __shared__ float wsum[8 * 8];                      // [warp][h]
    __shared__ ull comb[128 * 2];                      // jg1 partials

    const int t = threadIdx.x;
    const int i = blockIdx.x >> 1;
    const int half = blockIdx.x & 1;
    const int jbase = half * 256;

    // ---- DMA 64 KB: edges[i, jbase..jbase+256, :] ----
    {
        const float* gsrc = edges + ((size_t)i * NROW + jbase) * ED;
        unsigned int sbase = (unsigned int)__cvta_generic_to_shared(e_s);
#pragma unroll
        for (int it = 0; it < 16; it++) {
            const int idx = t + it * 256;             // 4096 float4s
            const int row = idx >> 4, c4 = idx & 15;
            cp16(sbase + (unsigned int)(row * ESTRIDE + c4 * 4) * 4,
                 gsrc + (size_t)row * ED + c4 * 4);
        }
        asm volatile("cp.async.commit_group;\n" ::: "memory");
    }

    // ---- overlap DMA with staging ----
#pragma unroll
    for (int k = 0; k < 2; k++) {
        const int idx = t + k * 256;
        t_s[(idx >> 6) * ESTRIDE + (idx & 63)] = g_t[i * (HH * ED) + idx];
    }
    const int av = adj[i * NROW + jbase + t];
    float sq[HH];
#pragma unroll
    for (int h = 0; h < HH; h++)
        sq[h] = g_simqk[((size_t)h * NROW + i) * NROW + jbase + t];

    asm volatile("cp.async.wait_group 0;\n" ::: "memory");
    __syncthreads();

    // ---- pass 1: thread = j; chunked edge preload (16 ull at a time) ----
    const int j = t;
    float ex[HH];
    {
        ull acc[HH];
#pragma unroll
        for (int h = 0; h < HH; h++) acc[h] = 0ull;
        const ull* ep = (const ull*)&e_s[j * ESTRIDE];
#pragma unroll
        for (int ch = 0; ch < 2; ch++) {
            ull er[16];
#pragma unroll
            for (int u = 0; u < 16; u++) er[u] = ep[ch * 16 + u];
#pragma unroll
            for (int h = 0; h < HH; h++) {
                const ull* tp = (const ull*)&t_s[h * ESTRIDE] + ch * 16;
                ull a = acc[h];
#pragma unroll
                for (int u = 0; u < 16; u++) a = fma2(er[u], tp[u], a);
                acc[h] = a;
            }
        }
#pragma unroll
        for (int h = 0; h < HH; h++) {
            const float simv = fmaf(hsum2(acc[h]), SCALE, sq[h]);
            ex[h] = av ? __expf(simv) : 0.f;
        }
    }

    // dup-packed esim for pass 2 + gmem copy for outv
#pragma unroll
    for (int h = 0; h < HH; h++) {
        sim_d[j * 9 + h] = pack2(ex[h], ex[h]);
        g_esim[((size_t)h * NROW + i) * NROW + jbase + j] = ex[h];
    }

    // ---- partial sums over j (warp shuffle + tiny smem tree) ----
    {
        float s[HH];
#pragma unroll
        for (int h = 0; h < HH; h++) s[h] = ex[h];
#pragma unroll
        for (int o = 16; o > 0; o >>= 1)
#pragma unroll
            for (int h = 0; h < HH; h++)
                s[h] += __shfl_xor_sync(0xffffffffu, s[h], o);
        if ((t & 31) == 0) {
            const int w = t >> 5;
#pragma unroll
            for (int h = 0; h < HH; h++) wsum[w * 8 + h] = s[h];
        }
    }
    __syncthreads();
    if (t < HH) {
        float s = 0.f;
#pragma unroll
        for (int w = 0; w < 8; w++) s += wsum[w * 8 + t];
        g_sump[half * (HH * NROW) + t * NROW + i] = s;
    }

    // ---- pass 2: thread = (jg, h, c4); private accumulation over 128 j ----
    {
        const int jg = t >> 7;          // 0..1
        const int h  = (t >> 4) & 7;    // 0..7
        const int c4 = t & 15;          // 0..15
        ull a0 = 0ull, a1 = 0ull;
        const int joff = jg * 128;
#pragma unroll 4
        for (int jj = 0; jj < 128; jj++) {
            const int jx = joff + jj;
            const ull sv = sim_d[jx * 9 + h];
            const longlong2 e2 = *(const longlong2*)&e_s[jx * ESTRIDE + c4 * 4];
            a0 = fma2(sv, (ull)e2.x, a0);
            a1 = fma2(sv, (ull)e2.y, a1);
        }
        if (jg == 1) {
            comb[(h * 16 + c4) * 2 + 0] = a0;
            comb[(h * 16 + c4) * 2 + 1] = a1;
        }
        __syncthreads();
        if (jg == 0) {
            a0 = add2(a0, comb[(h * 16 + c4) * 2 + 0]);
            a1 = add2(a1, comb[(h * 16 + c4) * 2 + 1]);
            const float2 A = unpack2(a0);
            const float2 B = unpack2(a1);
            *(float4*)&g_aggu[((size_t)(half * NROW + i) * HH + h) * ED + c4 * 4] =
                make_float4(A.x, A.y, B.x, B.y);
        }
    }
}

// ---------------------------------------------------------------------------
// Kernel B2: combine halves; out = (aggu*inv) @ We + rs*be; emit g_inv.
// grid (16 i-tiles of 32, 8 heads) = 128 blocks -> single wave.
// ---------------------------------------------------------------------------
__global__ __launch_bounds__(256) void finish_kernel(
    const float* __restrict__ We, const float* __restrict__ be,
    float* __restrict__ out)
{
    __shared__ float we_s[ED * DD];     // [c][d] 8 KB
    __shared__ float agg_s[32 * ED];    // [r][c] 8 KB
    __shared__ float inv_s[32], rs_s[32];

    const int t = threadIdx.x;
    const int i0 = blockIdx.x * 32;
    const int h  = blockIdx.y;

#pragma unroll
    for (int k = 0; k < 8; k++) {
        const int idx = t + k * 256;    // c = idx>>5, d = idx&31
        we_s[idx] = We[(idx >> 5) * INNER + h * DD + (idx & 31)];
    }
#pragma unroll
    for (int k = 0; k < 8; k++) {
        const int idx = t + k * 256;    // r = idx>>6, c = idx&63
        const int rr = idx >> 6, c = idx & 63;
        agg_s[idx] = g_aggu[((size_t)(i0 + rr) * HH + h) * ED + c]
                   + g_aggu[((size_t)(NROW + i0 + rr) * HH + h) * ED + c];
    }
    if (t < 32) {
        const float s = g_sump[h * NROW + i0 + t]
                      + g_sump[HH * NROW + h * NROW + i0 + t];
        const float inv = s > 0.f ? 1.f / s : 0.f;
        inv_s[t] = inv;
        rs_s[t]  = s > 0.f ? 1.f : 0.f;
        g_inv[h * NROW + i0 + t] = inv;
    }
    __syncthreads();

    const int d  = t & 31;
    const int r0 = t >> 5;              // rows r0, r0+8, r0+16, r0+24
    float acc[4] = {0.f, 0.f, 0.f, 0.f};
#pragma unroll 8
    for (int c = 0; c < ED; c++) {
        const float w = we_s[c * DD + d];
#pragma unroll
        for (int m = 0; m < 4; m++)
            acc[m] = fmaf(agg_s[(r0 + m * 8) * ED + c], w, acc[m]);
    }
    const float bev = be[h * DD + d];
#pragma unroll
    for (int m = 0; m < 4; m++) {
        const int r = r0 + m * 8;
        out[(i0 + r) * INNER + h * DD + d] =
            fmaf(rs_s[r], bev, acc[m] * inv_s[r]);
    }
}

// ---------------------------------------------------------------------------
// Kernel C: out += (esim*inv) @ v, j split 4-ways, atomicAdd epilogue.
// ---------------------------------------------------------------------------
#define VPAD 130
__global__ __launch_bounds__(256) void outv_kernel(float* __restrict__ out)
{
    __shared__ float a_s[32 * 128];                   // esim tile [i-local][j-local]
    __shared__ __align__(8) float v_sT[32 * VPAD];    // v transposed [d][j-local]
    __shared__ float inv_s[32];
    const int t = threadIdx.x;
    const int i0 = blockIdx.x * 32;
    const int h  = blockIdx.y;
    const int j0 = blockIdx.z * 128;

    if (t < 32) inv_s[t] = g_inv[h * NROW + i0 + t];
#pragma unroll
    for (int f = 0; f < 4; f++) {
        const int idx = t + f * 256;          // 1024 float4s esim 32x128
        const int row = idx >> 5, c4 = idx & 31;
        *(float4*)&a_s[row * 128 + c4 * 4] =
            *(const float4*)&g_esim[((size_t)h * NROW + i0 + row) * NROW + j0 + c4 * 4];
    }
#pragma unroll
    for (int f = 0; f < 4; f++) {
        const int idx = t + f * 256;          // 1024 float4s v 128x32 (transpose)
        const int row = idx >> 3, c4 = idx & 7;
        const float4 v4 = *(const float4*)&g_v[(j0 + row) * INNER + h * DD + c4 * 4];
        v_sT[(c4 * 4 + 0) * VPAD + row] = v4.x;
        v_sT[(c4 * 4 + 1) * VPAD + row] = v4.y;
        v_sT[(c4 * 4 + 2) * VPAD + row] = v4.z;
        v_sT[(c4 * 4 + 3) * VPAD + row] = v4.w;
    }
    __syncthreads();

    const int d  = t & 31;
    const int i4 = t >> 5;
    ull acc[4] = {0ull, 0ull, 0ull, 0ull};
#pragma unroll 8
    for (int jp = 0; jp < 64; jp++) {
        const ull v2 = *(const ull*)&v_sT[d * VPAD + jp * 2];
#pragma unroll
        for (int m = 0; m < 4; m++) {
            const ull av2 = *(const ull*)&a_s[(i4 + m * 8) * 128 + jp * 2];
            acc[m] = fma2(av2, v2, acc[m]);
        }
    }
#pragma unroll
    for (int m = 0; m < 4; m++)
        atomicAdd(&out[(i0 + i4 + m * 8) * INNER + h * DD + d],
                  hsum2(acc[m]) * inv_s[i4 + m * 8]);
}

// ---------------------------------------------------------------------------
extern "C" void kernel_launch(void* const* d_in, const int* in_sizes, int n_in,
                              void* d_out, int out_size)
{
    const float* nodes = (const float*)d_in[0];
    const float* edges = (const float*)d_in[1];
    const int*   adj   = (const int*)d_in[2];
    const float* Wq    = (const float*)d_in[3];
    const float* bq    = (const float*)d_in[4];
    const float* Wk    = (const float*)d_in[5];
    const float* bk    = (const float*)d_in[6];
    const float* Wv    = (const float*)d_in[7];
    const float* bv    = (const float*)d_in[8];
    const float* We    = (const float*)d_in[9];
    const float* be    = (const float*)d_in[10];
    float* out = (float*)d_out;

    cudaFuncSetAttribute(simagg_kernel,
                         cudaFuncAttributeMaxDynamicSharedMemorySize, HSMEM);

    proj_kernel<<<128, 256>>>(nodes, Wq, bq, Wk, bk, Wv, bv, We, be);
    qk_kernel<<<dim3(16, 16, 8), 256>>>();
    simagg_kernel<<<1024, 256, HSMEM>>>(edges, adj);
    finish_kernel<<<dim3(16, 8), 256>>>(We, be, out);
    outv_kernel<<<dim3(16, 8, 4), 256>>>(out);
}

// round 8
// speedup vs baseline: 1.3849x; 1.1294x over previous
#include <cuda_runtime.h>
#include <cstdint>

#define NROW 512
#define HH 8
#define DD 32
#define INNER 256
#define ED 64
#define SCALE 0.17677669529663687f  // 1/sqrt(32)
#define ESTRIDE 68                  // padded row stride (floats), 16B-aligned rows
#define HSMEM (256 * ESTRIDE * 4)   // 69632 B dynamic smem (half row)
#define SPAD 260                    // sim_f row stride (floats), 16B-aligned

// Scratch (device globals; no allocation in kernel_launch).
__device__ float g_q[NROW * INNER];
__device__ float g_k[NROW * INNER];
__device__ float g_v[NROW * INNER];
__device__ float g_t[NROW * HH * ED];        // [i][h][c]  t = We_h^T q_{h,i}
__device__ float g_qbe[NROW * HH];           // q_{h,i} . be_h
__device__ float g_simqk[HH * NROW * NROW];
__device__ float g_esim[HH * NROW * NROW];   // unnormalized exp*adj
__device__ float g_aggu[2 * NROW * HH * ED]; // [half][i][h][c] partial agg
__device__ float g_sump[2 * HH * NROW];      // [half][h][i] partial sums

typedef unsigned long long ull;

__device__ __forceinline__ ull fma2(ull a, ull b, ull c) {
    ull d;
    asm("fma.rn.f32x2 %0, %1, %2, %3;" : "=l"(d) : "l"(a), "l"(b), "l"(c));
    return d;
}
__device__ __forceinline__ ull add2(ull a, ull b) {
    ull d;
    asm("add.rn.f32x2 %0, %1, %2;" : "=l"(d) : "l"(a), "l"(b));
    return d;
}
__device__ __forceinline__ ull pack2(float lo, float hi) {
    ull d;
    asm("mov.b64 %0, {%1, %2};" : "=l"(d) : "f"(lo), "f"(hi));
    return d;
}
__device__ __forceinline__ float2 unpack2(ull v) {
    float lo, hi;
    asm("mov.b64 {%0, %1}, %2;" : "=f"(lo), "=f"(hi) : "l"(v));
    return make_float2(lo, hi);
}
__device__ __forceinline__ float hsum2(ull v) {
    float2 f = unpack2(v);
    return f.x + f.y;
}
__device__ __forceinline__ void cp16(unsigned int daddr, const void* gptr) {
    asm volatile("cp.async.cg.shared.global [%0], [%1], 16;\n"
                 :: "r"(daddr), "l"(gptr));
}

// ---------------------------------------------------------------------------
// Kernel A: q/k/v projections + t = We_h^T q + qbe.  4 rows per block.
// ---------------------------------------------------------------------------
__global__ __launch_bounds__(256) void proj_kernel(
    const float* __restrict__ nodes,
    const float* __restrict__ Wq, const float* __restrict__ bq,
    const float* __restrict__ Wk, const float* __restrict__ bk,
    const float* __restrict__ Wv, const float* __restrict__ bv,
    const float* __restrict__ We, const float* __restrict__ be)
{
    __shared__ float node_s[4][128];
    __shared__ float q_s[4][INNER];
    const int t = threadIdx.x;
    const int i0 = blockIdx.x * 4;

    for (int idx = t; idx < 4 * 128; idx += 256)
        node_s[idx >> 7][idx & 127] = nodes[i0 * 128 + idx];
    __syncthreads();

    float aq[4], ak[4], av[4];
    const float bqv = bq[t], bkv = bk[t], bvv = bv[t];
#pragma unroll
    for (int r = 0; r < 4; r++) { aq[r] = bqv; ak[r] = bkv; av[r] = bvv; }

#pragma unroll 8
    for (int k = 0; k < 128; k++) {
        const float wq = Wq[k * INNER + t];
        const float wk = Wk[k * INNER + t];
        const float wv = Wv[k * INNER + t];
#pragma unroll
        for (int r = 0; r < 4; r++) {
            const float nv = node_s[r][k];
            aq[r] = fmaf(nv, wq, aq[r]);
            ak[r] = fmaf(nv, wk, ak[r]);
            av[r] = fmaf(nv, wv, av[r]);
        }
    }
#pragma unroll
    for (int r = 0; r < 4; r++) {
        g_q[(i0 + r) * INNER + t] = aq[r];
        g_k[(i0 + r) * INNER + t] = ak[r];
        g_v[(i0 + r) * INNER + t] = av[r];
        q_s[r][t] = aq[r];
    }
    __syncthreads();

    // t[i][h][c] = sum_d We[c, h*32+d] * q[i, h*32+d]
    for (int idx = t; idx < HH * ED; idx += 256) {
        const int h = idx >> 6, c = idx & 63;
        float acc[4] = {0.f, 0.f, 0.f, 0.f};
        const float* wrow = We + c * INNER + h * DD;
#pragma unroll
        for (int d = 0; d < DD; d++) {
            const float w = wrow[d];
#pragma unroll
            for (int r = 0; r < 4; r++)
                acc[r] = fmaf(w, q_s[r][h * DD + d], acc[r]);
        }
#pragma unroll
        for (int r = 0; r < 4; r++)
            g_t[(i0 + r) * (HH * ED) + idx] = acc[r];
    }

    if (t < 4 * HH) {
        const int r = t >> 3, h = t & 7;
        float s = 0.f;
#pragma unroll
        for (int d = 0; d < DD; d++)
            s = fmaf(q_s[r][h * DD + d], be[h * DD + d], s);
        g_qbe[(i0 + r) * HH + h] = s;
    }
}

// ---------------------------------------------------------------------------
// Kernel QK: simqk[h][i][j] = (q_h[i].k_h[j] + qbe[i][h]) * SCALE
// ---------------------------------------------------------------------------
__global__ __launch_bounds__(256) void qk_kernel()
{
    __shared__ float q_s[32][33];
    __shared__ float k_s[32][33];
    const int t = threadIdx.x;
    const int j0 = blockIdx.x * 32;
    const int i0 = blockIdx.y * 32;
    const int h  = blockIdx.z;

    {
        const int r = t >> 3, c4 = (t & 7) * 4;
        const float4 qv = *(const float4*)&g_q[(i0 + r) * INNER + h * DD + c4];
        q_s[r][c4 + 0] = qv.x; q_s[r][c4 + 1] = qv.y;
        q_s[r][c4 + 2] = qv.z; q_s[r][c4 + 3] = qv.w;
        const float4 kv = *(const float4*)&g_k[(j0 + r) * INNER + h * DD + c4];
        k_s[r][c4 + 0] = kv.x; k_s[r][c4 + 1] = kv.y;
        k_s[r][c4 + 2] = kv.z; k_s[r][c4 + 3] = kv.w;
    }
    __syncthreads();

    const int tx = t & 31, ty = t >> 5;
    float acc[4] = {0.f, 0.f, 0.f, 0.f};
#pragma unroll
    for (int d = 0; d < 32; d++) {
        const float kv = k_s[tx][d];
#pragma unroll
        for (int m = 0; m < 4; m++)
            acc[m] = fmaf(q_s[ty + m * 8][d], kv, acc[m]);
    }
#pragma unroll
    for (int m = 0; m < 4; m++) {
        const int i = i0 + ty + m * 8;
        g_simqk[((size_t)h * NROW + i) * NROW + j0 + tx] =
            (acc[m] + g_qbe[i * HH + h]) * SCALE;
    }
}

// ---------------------------------------------------------------------------
// Kernel B: half-row sim + exp + partial sums + partial unnormalized agg.
// grid 1024 = (row i) x (half), 256 threads, occ 2.
// Pass 2: thread = (jgroup, c-quad) holds ALL 8 heads in registers, so each
// edge element is read from smem exactly once (was 8x).
// ---------------------------------------------------------------------------
__global__ __launch_bounds__(256, 2) void simagg_kernel(
    const float* __restrict__ edges, const int* __restrict__ adj)
{
    extern __shared__ __align__(16) float e_s[];        // [256][ESTRIDE]
    __shared__ __align__(16) float t_s[HH * ESTRIDE];
    __shared__ __align__(16) float sim_f[HH * SPAD];    // [h][j] esim
    __shared__ float wsum[8 * 8];                       // [warp][h]

    const int t = threadIdx.x;
    const int i = blockIdx.x >> 1;
    const int half = blockIdx.x & 1;
    const int jbase = half * 256;

    // ---- DMA 64 KB: edges[i, jbase..jbase+256, :] ----
    {
        const float* gsrc = edges + ((size_t)i * NROW + jbase) * ED;
        unsigned int sbase = (unsigned int)__cvta_generic_to_shared(e_s);
#pragma unroll
        for (int it = 0; it < 16; it++) {
            const int idx = t + it * 256;             // 4096 float4s
            const int row = idx >> 4, c4 = idx & 15;
            cp16(sbase + (unsigned int)(row * ESTRIDE + c4 * 4) * 4,
                 gsrc + (size_t)row * ED + c4 * 4);
        }
        asm volatile("cp.async.commit_group;\n" ::: "memory");
    }

    // ---- overlap DMA with staging ----
#pragma unroll
    for (int k = 0; k < 2; k++) {
        const int idx = t + k * 256;
        t_s[(idx >> 6) * ESTRIDE + (idx & 63)] = g_t[i * (HH * ED) + idx];
    }
    const int av = adj[i * NROW + jbase + t];
    float sq[HH];
#pragma unroll
    for (int h = 0; h < HH; h++)
        sq[h] = g_simqk[((size_t)h * NROW + i) * NROW + jbase + t];

    asm volatile("cp.async.wait_group 0;\n" ::: "memory");
    __syncthreads();

    // ---- pass 1: thread = j; 16B loads throughout ----
    const int j = t;
    float ex[HH];
    {
        ull acc[HH];
#pragma unroll
        for (int h = 0; h < HH; h++) acc[h] = 0ull;
        const longlong2* ep = (const longlong2*)&e_s[j * ESTRIDE];
#pragma unroll
        for (int ch = 0; ch < 2; ch++) {
            longlong2 er[8];                          // 32 floats
#pragma unroll
            for (int u = 0; u < 8; u++) er[u] = ep[ch * 8 + u];
#pragma unroll
            for (int h = 0; h < HH; h++) {
                const longlong2* tp = (const longlong2*)&t_s[h * ESTRIDE] + ch * 8;
                ull a = acc[h];
#pragma unroll
                for (int u = 0; u < 8; u++) {
                    const longlong2 tv = tp[u];
                    a = fma2((ull)er[u].x, (ull)tv.x, a);
                    a = fma2((ull)er[u].y, (ull)tv.y, a);
                }
                acc[h] = a;
            }
        }
#pragma unroll
        for (int h = 0; h < HH; h++) {
            const float simv = fmaf(hsum2(acc[h]), SCALE, sq[h]);
            ex[h] = av ? __expf(simv) : 0.f;
        }
    }

    // esim: smem (for pass 2) + gmem (for outv)
#pragma unroll
    for (int h = 0; h < HH; h++) {
        sim_f[h * SPAD + j] = ex[h];
        g_esim[((size_t)h * NROW + i) * NROW + jbase + j] = ex[h];
    }

    // ---- partial sums over j ----
    {
        float s[HH];
#pragma unroll
        for (int h = 0; h < HH; h++) s[h] = ex[h];
#pragma unroll
        for (int o = 16; o > 0; o >>= 1)
#pragma unroll
            for (int h = 0; h < HH; h++)
                s[h] += __shfl_xor_sync(0xffffffffu, s[h], o);
        if ((t & 31) == 0) {
            const int w = t >> 5;
#pragma unroll
            for (int h = 0; h < HH; h++) wsum[w * 8 + h] = s[h];
        }
    }
    __syncthreads();
    if (t < HH) {
        float s = 0.f;
#pragma unroll
        for (int w = 0; w < 8; w++) s += wsum[w * 8 + t];
        g_sump[half * (HH * NROW) + t * NROW + i] = s;
    }

    // ---- pass 2: thread = (jg 0..7, c4 0..15); 8 heads in registers ----
    ull pa[HH][2];
    const int jg = t >> 4;          // 0..15, only 0..7 active
    const int c4 = t & 15;
    if (jg < 8) {
#pragma unroll
        for (int h = 0; h < HH; h++) { pa[h][0] = 0ull; pa[h][1] = 0ull; }
        const int joff = jg * 32;
#pragma unroll 2
        for (int k4 = 0; k4 < 8; k4++) {
            float4 s4[HH];
#pragma unroll
            for (int h = 0; h < HH; h++)
                s4[h] = *(const float4*)&sim_f[h * SPAD + joff + k4 * 4];
#pragma unroll
            for (int kk = 0; kk < 4; kk++) {
                const int jx = joff + k4 * 4 + kk;
                const longlong2 e2 = *(const longlong2*)&e_s[jx * ESTRIDE + c4 * 4];
#pragma unroll
                for (int h = 0; h < HH; h++) {
                    const float sv = (kk == 0) ? s4[h].x : (kk == 1) ? s4[h].y
                                   : (kk == 2) ? s4[h].z : s4[h].w;
                    const ull sp = pack2(sv, sv);
                    pa[h][0] = fma2(sp, (ull)e2.x, pa[h][0]);
                    pa[h][1] = fma2(sp, (ull)e2.y, pa[h][1]);
                }
            }
        }
    }
    __syncthreads();                 // e_s reads done; alias it for partials
    float4* part = (float4*)e_s;     // [jg][h][c4] float4
    if (jg < 8) {
#pragma unroll
        for (int h = 0; h < HH; h++) {
            const float2 A = unpack2(pa[h][0]);
            const float2 B = unpack2(pa[h][1]);
            part[(jg * 8 + h) * 16 + c4] = make_float4(A.x, A.y, B.x, B.y);
        }
    }
    __syncthreads();
    if (t < 128) {                   // h = t>>4, c4 = t&15
        const int h = t >> 4;
        float4 s = part[h * 16 + c4];
#pragma unroll
        for (int g = 1; g < 8; g++) {
            const float4 p = part[(g * 8 + h) * 16 + c4];
            s.x += p.x; s.y += p.y; s.z += p.z; s.w += p.w;
        }
        *(float4*)&g_aggu[((size_t)(half * NROW + i) * HH + h) * ED + c4 * 4] = s;
    }
}

// ---------------------------------------------------------------------------
// Kernel C: out = inv * (esim @ v + aggu @ We) + rs * be.
// grid (16 i-tiles, 8 heads) = 128 blocks (single wave), no atomics.
// ---------------------------------------------------------------------------
#define VPAD 130
__global__ __launch_bounds__(256) void outv_kernel(
    const float* __restrict__ We, const float* __restrict__ be,
    float* __restrict__ out)
{
    __shared__ float a_s[32 * 128];                   // esim tile
    __shared__ __align__(8) float v_sT[32 * VPAD];    // v transposed [d][j]
    __shared__ float we_s[ED * DD];                   // [c][d]
    __shared__ float agg_s[32 * ED];                  // [r][c]
    __shared__ float inv_s[32], rs_s[32];

    const int t = threadIdx.x;
    const int i0 = blockIdx.x * 32;
    const int h  = blockIdx.y;
    const int d  = t & 31;
    const int r0 = t >> 5;

    // stage We, combined agg, inv/rs
#pragma unroll
    for (int k = 0; k < 8; k++) {
        const int idx = t + k * 256;                  // c = idx>>5, dd = idx&31
        we_s[idx] = We[(idx >> 5) * INNER + h * DD + (idx & 31)];
    }
#pragma unroll
    for (int k = 0; k < 8; k++) {
        const int idx = t + k * 256;                  // r = idx>>6, c = idx&63
        const int rr = idx >> 6, c = idx & 63;
        agg_s[idx] = g_aggu[((size_t)(i0 + rr) * HH + h) * ED + c]
                   + g_aggu[((size_t)(NROW + i0 + rr) * HH + h) * ED + c];
    }
    if (t < 32) {
        const float s = g_sump[h * NROW + i0 + t]
                      + g_sump[HH * NROW + h * NROW + i0 + t];
        inv_s[t] = s > 0.f ? 1.f / s : 0.f;
        rs_s[t]  = s > 0.f ? 1.f : 0.f;
    }
    __syncthreads();

    // edge term (unnormalized): acc[m] = agg[r]·We[:,d]
    float acc[4] = {0.f, 0.f, 0.f, 0.f};
#pragma unroll 8
    for (int c = 0; c < ED; c++) {
        const float w = we_s[c * DD + d];
#pragma unroll
        for (int m = 0; m < 4; m++)
            acc[m] = fmaf(agg_s[(r0 + m * 8) * ED + c], w, acc[m]);
    }

    // v term over 4 j-chunks of 128
    ull acc2[4] = {0ull, 0ull, 0ull, 0ull};
    for (int ch = 0; ch < 4; ch++) {
        const int j0 = ch * 128;
        __syncthreads();
#pragma unroll
        for (int f = 0; f < 4; f++) {
            const int idx = t + f * 256;              // esim 32x128
            const int row = idx >> 5, c4 = idx & 31;
            *(float4*)&a_s[row * 128 + c4 * 4] =
                *(const float4*)&g_esim[((size_t)h * NROW + i0 + row) * NROW + j0 + c4 * 4];
        }
#pragma unroll
        for (int f = 0; f < 4; f++) {
            const int idx = t + f * 256;              // v 128x32 transpose
            const int row = idx >> 3, c4 = idx & 7;
            const float4 v4 = *(const float4*)&g_v[(j0 + row) * INNER + h * DD + c4 * 4];
            v_sT[(c4 * 4 + 0) * VPAD + row] = v4.x;
            v_sT[(c4 * 4 + 1) * VPAD + row] = v4.y;
            v_sT[(c4 * 4 + 2) * VPAD + row] = v4.z;
            v_sT[(c4 * 4 + 3) * VPAD + row] = v4.w;
        }
        __syncthreads();
#pragma unroll 8
        for (int jp = 0; jp < 64; jp++) {
            const ull v2 = *(const ull*)&v_sT[d * VPAD + jp * 2];
#pragma unroll
            for (int m = 0; m < 4; m++) {
                const ull av2 = *(const ull*)&a_s[(r0 + m * 8) * 128 + jp * 2];
                acc2[m] = fma2(av2, v2, acc2[m]);
            }
        }
    }

    const float bev = be[h * DD + d];
#pragma unroll
    for (int m = 0; m < 4; m++) {
        const int r = r0 + m * 8;
        out[(i0 + r) * INNER + h * DD + d] =
            fmaf(rs_s[r], bev, (acc[m] + hsum2(acc2[m])) * inv_s[r]);
    }
}

// ---------------------------------------------------------------------------
extern "C" void kernel_launch(void* const* d_in, const int* in_sizes, int n_in,
                              void* d_out, int out_size)
{
    const float* nodes = (const float*)d_in[0];
    const float* edges = (const float*)d_in[1];
    const int*   adj   = (const int*)d_in[2];
    const float* Wq    = (const float*)d_in[3];
    const float* bq    = (const float*)d_in[4];
    const float* Wk    = (const float*)d_in[5];
    const float* bk    = (const float*)d_in[6];
    const float* Wv    = (const float*)d_in[7];
    const float* bv    = (const float*)d_in[8];
    const float* We    = (const float*)d_in[9];
    const float* be    = (const float*)d_in[10];
    float* out = (float*)d_out;

    cudaFuncSetAttribute(simagg_kernel,
                         cudaFuncAttributeMaxDynamicSharedMemorySize, HSMEM);

    proj_kernel<<<128, 256>>>(nodes, Wq, bq, Wk, bk, Wv, bv, We, be);
    qk_kernel<<<dim3(16, 16, 8), 256>>>();
    simagg_kernel<<<1024, 256, HSMEM>>>(edges, adj);
    outv_kernel<<<dim3(16, 8), 256>>>(We, be, out);
}

// round 10
// speedup vs baseline: 1.4232x; 1.0277x over previous
#include <cuda_runtime.h>
#include <cstdint>

#define NROW 512
#define HH 8
#define DD 32
#define INNER 256
#define ED 64
#define SCALE 0.17677669529663687f  // 1/sqrt(32)
#define ESTRIDE 68                  // padded row stride (floats), 16B-aligned rows
#define HSMEM (256 * ESTRIDE * 4)   // 69632 B dynamic smem (half row)
#define SPAD 260                    // sim_f row stride (floats), 16B-aligned
#define VPAD 130                    // v_sT row stride (8B-aligned, conflict-free)

// Scratch (device globals; no allocation in kernel_launch).
__device__ float g_q[NROW * INNER];
__device__ float g_k[NROW * INNER];
__device__ float g_v[NROW * INNER];
__device__ float g_t[NROW * HH * ED];        // [i][h][c]  t = We_h^T q_{h,i}
__device__ float g_qbe[NROW * HH];           // q_{h,i} . be_h
__device__ float g_simqk[HH * NROW * NROW];
__device__ float g_esim[HH * NROW * NROW];   // unnormalized exp*adj
__device__ float g_aggu[2 * NROW * HH * ED]; // [half][i][h][c] partial agg
__device__ float g_sump[2 * HH * NROW];      // [half][h][i] partial sums

typedef unsigned long long ull;

__device__ __forceinline__ ull fma2(ull a, ull b, ull c) {
    ull d;
    asm("fma.rn.f32x2 %0, %1, %2, %3;" : "=l"(d) : "l"(a), "l"(b), "l"(c));
    return d;
}
__device__ __forceinline__ ull pack2(float lo, float hi) {
    ull d;
    asm("mov.b64 %0, {%1, %2};" : "=l"(d) : "f"(lo), "f"(hi));
    return d;
}
__device__ __forceinline__ float2 unpack2(ull v) {
    float lo, hi;
    asm("mov.b64 {%0, %1}, %2;" : "=f"(lo), "=f"(hi) : "l"(v));
    return make_float2(lo, hi);
}
__device__ __forceinline__ float hsum2(ull v) {
    float2 f = unpack2(v);
    return f.x + f.y;
}
__device__ __forceinline__ void cp16(unsigned int daddr, const void* gptr) {
    asm volatile("cp.async.cg.shared.global [%0], [%1], 16;\n"
                 :: "r"(daddr), "l"(gptr));
}

// ---------------------------------------------------------------------------
// Kernel A: q/k/v projections + t = We_h^T q + qbe.  4 rows per block.
// ---------------------------------------------------------------------------
__global__ __launch_bounds__(256) void proj_kernel(
    const float* __restrict__ nodes,
    const float* __restrict__ Wq, const float* __restrict__ bq,
    const float* __restrict__ Wk, const float* __restrict__ bk,
    const float* __restrict__ Wv, const float* __restrict__ bv,
    const float* __restrict__ We, const float* __restrict__ be)
{
    __shared__ float node_s[4][128];
    __shared__ float q_s[4][INNER];
    const int t = threadIdx.x;
    const int i0 = blockIdx.x * 4;

    for (int idx = t; idx < 4 * 128; idx += 256)
        node_s[idx >> 7][idx & 127] = nodes[i0 * 128 + idx];
    __syncthreads();

    float aq[4], ak[4], av[4];
    const float bqv = bq[t], bkv = bk[t], bvv = bv[t];
#pragma unroll
    for (int r = 0; r < 4; r++) { aq[r] = bqv; ak[r] = bkv; av[r] = bvv; }

#pragma unroll 8
    for (int k = 0; k < 128; k++) {
        const float wq = Wq[k * INNER + t];
        const float wk = Wk[k * INNER + t];
        const float wv = Wv[k * INNER + t];
#pragma unroll
        for (int r = 0; r < 4; r++) {
            const float nv = node_s[r][k];
            aq[r] = fmaf(nv, wq, aq[r]);
            ak[r] = fmaf(nv, wk, ak[r]);
            av[r] = fmaf(nv, wv, av[r]);
        }
    }
#pragma unroll
    for (int r = 0; r < 4; r++) {
        g_q[(i0 + r) * INNER + t] = aq[r];
        g_k[(i0 + r) * INNER + t] = ak[r];
        g_v[(i0 + r) * INNER + t] = av[r];
        q_s[r][t] = aq[r];
    }
    __syncthreads();

    // t[i][h][c] = sum_d We[c, h*32+d] * q[i, h*32+d]
    for (int idx = t; idx < HH * ED; idx += 256) {
        const int h = idx >> 6, c = idx & 63;
        float acc[4] = {0.f, 0.f, 0.f, 0.f};
        const float* wrow = We + c * INNER + h * DD;
#pragma unroll
        for (int d = 0; d < DD; d++) {
            const float w = wrow[d];
#pragma unroll
            for (int r = 0; r < 4; r++)
                acc[r] = fmaf(w, q_s[r][h * DD + d], acc[r]);
        }
#pragma unroll
        for (int r = 0; r < 4; r++)
            g_t[(i0 + r) * (HH * ED) + idx] = acc[r];
    }

    if (t < 4 * HH) {
        const int r = t >> 3, h = t & 7;
        float s = 0.f;
#pragma unroll
        for (int d = 0; d < DD; d++)
            s = fmaf(q_s[r][h * DD + d], be[h * DD + d], s);
        g_qbe[(i0 + r) * HH + h] = s;
    }
}

// ---------------------------------------------------------------------------
// Kernel QK: simqk[h][i][j] = (q_h[i].k_h[j] + qbe[i][h]) * SCALE
// ---------------------------------------------------------------------------
__global__ __launch_bounds__(256) void qk_kernel()
{
    __shared__ float q_s[32][33];
    __shared__ float k_s[32][33];
    const int t = threadIdx.x;
    const int j0 = blockIdx.x * 32;
    const int i0 = blockIdx.y * 32;
    const int h  = blockIdx.z;

    {
        const int r = t >> 3, c4 = (t & 7) * 4;
        const float4 qv = *(const float4*)&g_q[(i0 + r) * INNER + h * DD + c4];
        q_s[r][c4 + 0] = qv.x; q_s[r][c4 + 1] = qv.y;
        q_s[r][c4 + 2] = qv.z; q_s[r][c4 + 3] = qv.w;
        const float4 kv = *(const float4*)&g_k[(j0 + r) * INNER + h * DD + c4];
        k_s[r][c4 + 0] = kv.x; k_s[r][c4 + 1] = kv.y;
        k_s[r][c4 + 2] = kv.z; k_s[r][c4 + 3] = kv.w;
    }
    __syncthreads();

    const int tx = t & 31, ty = t >> 5;
    float acc[4] = {0.f, 0.f, 0.f, 0.f};
#pragma unroll
    for (int d = 0; d < 32; d++) {
        const float kv = k_s[tx][d];
#pragma unroll
        for (int m = 0; m < 4; m++)
            acc[m] = fmaf(q_s[ty + m * 8][d], kv, acc[m]);
    }
#pragma unroll
    for (int m = 0; m < 4; m++) {
        const int i = i0 + ty + m * 8;
        g_simqk[((size_t)h * NROW + i) * NROW + j0 + tx] =
            (acc[m] + g_qbe[i * HH + h]) * SCALE;
    }
}

// ---------------------------------------------------------------------------
// Kernel B: half-row sim + exp + partial sums + partial unnormalized agg.
// grid 1024 = (row i) x (half), 256 threads, occ 2. DMA split into two
// column-groups (c 0..31 then 32..63); pass 1 starts on the first group.
// Pass 2: all 256 threads = (jgroup 0..15, c-quad 0..15), 8 heads in regs.
// ---------------------------------------------------------------------------
__global__ __launch_bounds__(256, 2) void simagg_kernel(
    const float* __restrict__ edges, const int* __restrict__ adj)
{
    extern __shared__ __align__(16) float e_s[];        // [256][ESTRIDE]
    __shared__ __align__(16) float t_s[HH * ESTRIDE];
    __shared__ __align__(16) float sim_f[HH * SPAD];    // [h][j] esim
    __shared__ float wsum[8 * 8];                       // [warp][h]

    const int t = threadIdx.x;
    const int i = blockIdx.x >> 1;
    const int half = blockIdx.x & 1;
    const int jbase = half * 256;

    // ---- DMA: group A = c4 0..7 (floats 0..31), group B = c4 8..15 ----
    {
        const float* gsrc = edges + ((size_t)i * NROW + jbase) * ED;
        unsigned int sbase = (unsigned int)__cvta_generic_to_shared(e_s);
#pragma unroll
        for (int it = 0; it < 8; it++) {
            const int idx = t + it * 256;             // 2048: row=idx>>3, c4=idx&7
            const int row = idx >> 3, c4 = idx & 7;
            cp16(sbase + (unsigned int)(row * ESTRIDE + c4 * 4) * 4,
                 gsrc + (size_t)row * ED + c4 * 4);
        }
        asm volatile("cp.async.commit_group;\n" ::: "memory");
#pragma unroll
        for (int it = 0; it < 8; it++) {
            const int idx = t + it * 256;
            const int row = idx >> 3, c4 = (idx & 7) + 8;
            cp16(sbase + (unsigned int)(row * ESTRIDE + c4 * 4) * 4,
                 gsrc + (size_t)row * ED + c4 * 4);
        }
        asm volatile("cp.async.commit_group;\n" ::: "memory");
    }

    // ---- overlap DMA with staging ----
#pragma unroll
    for (int k = 0; k < 2; k++) {
        const int idx = t + k * 256;
        t_s[(idx >> 6) * ESTRIDE + (idx & 63)] = g_t[i * (HH * ED) + idx];
    }
    const int av = adj[i * NROW + jbase + t];
    float sq[HH];
#pragma unroll
    for (int h = 0; h < HH; h++)
        sq[h] = g_simqk[((size_t)h * NROW + i) * NROW + jbase + t];

    // ---- pass 1: thread = j. Group A = ep[0..7] (floats 0..31), B = ep[8..15] ----
    const int j = t;
    ull acc[HH];
#pragma unroll
    for (int h = 0; h < HH; h++) acc[h] = 0ull;
    const longlong2* ep = (const longlong2*)&e_s[j * ESTRIDE];

    asm volatile("cp.async.wait_group 1;\n" ::: "memory");
    __syncthreads();
    {
        longlong2 er[8];
#pragma unroll
        for (int u = 0; u < 8; u++) er[u] = ep[u];
#pragma unroll
        for (int h = 0; h < HH; h++) {
            const longlong2* tp = (const longlong2*)&t_s[h * ESTRIDE];
            ull a = acc[h];
#pragma unroll
            for (int u = 0; u < 8; u++) {
                const longlong2 tv = tp[u];
                a = fma2((ull)er[u].x, (ull)tv.x, a);
                a = fma2((ull)er[u].y, (ull)tv.y, a);
            }
            acc[h] = a;
        }
    }
    asm volatile("cp.async.wait_group 0;\n" ::: "memory");
    __syncthreads();
    float ex[HH];
    {
        longlong2 er[8];
#pragma unroll
        for (int u = 0; u < 8; u++) er[u] = ep[8 + u];
#pragma unroll
        for (int h = 0; h < HH; h++) {
            const longlong2* tp = (const longlong2*)&t_s[h * ESTRIDE] + 8;
            ull a = acc[h];
#pragma unroll
            for (int u = 0; u < 8; u++) {
                const longlong2 tv = tp[u];
                a = fma2((ull)er[u].x, (ull)tv.x, a);
                a = fma2((ull)er[u].y, (ull)tv.y, a);
            }
            const float simv = fmaf(hsum2(a), SCALE, sq[h]);
            ex[h] = av ? __expf(simv) : 0.f;
        }
    }

    // esim: smem (for pass 2) + gmem (for outv)
#pragma unroll
    for (int h = 0; h < HH; h++) {
        sim_f[h * SPAD + j] = ex[h];
        g_esim[((size_t)h * NROW + i) * NROW + jbase + j] = ex[h];
    }

    // ---- partial sums over j ----
    {
        float s[HH];
#pragma unroll
        for (int h = 0; h < HH; h++) s[h] = ex[h];
#pragma unroll
        for (int o = 16; o > 0; o >>= 1)
#pragma unroll
            for (int h = 0; h < HH; h++)
                s[h] += __shfl_xor_sync(0xffffffffu, s[h], o);
        if ((t & 31) == 0) {
            const int w = t >> 5;
#pragma unroll
            for (int h = 0; h < HH; h++) wsum[w * 8 + h] = s[h];
        }
    }
    __syncthreads();
    if (t < HH) {
        float s = 0.f;
#pragma unroll
        for (int w = 0; w < 8; w++) s += wsum[w * 8 + t];
        g_sump[half * (HH * NROW) + t * NROW + i] = s;
    }

    // ---- pass 2: thread = (jg 0..15, c4 0..15); 16 j per group ----
    ull pa[HH][2];
    const int jg = t >> 4;
    const int c4 = t & 15;
#pragma unroll
    for (int h = 0; h < HH; h++) { pa[h][0] = 0ull; pa[h][1] = 0ull; }
    {
        const int joff = jg * 16;
#pragma unroll
        for (int k4 = 0; k4 < 4; k4++) {
            float4 s4[HH];
#pragma unroll
            for (int h = 0; h < HH; h++)
                s4[h] = *(const float4*)&sim_f[h * SPAD + joff + k4 * 4];
#pragma unroll
            for (int kk = 0; kk < 4; kk++) {
                const int jx = joff + k4 * 4 + kk;
                const longlong2 e2 = *(const longlong2*)&e_s[jx * ESTRIDE + c4 * 4];
#pragma unroll
                for (int h = 0; h < HH; h++) {
                    const float sv = (kk == 0) ? s4[h].x : (kk == 1) ? s4[h].y
                                   : (kk == 2) ? s4[h].z : s4[h].w;
                    const ull sp = pack2(sv, sv);
                    pa[h][0] = fma2(sp, (ull)e2.x, pa[h][0]);
                    pa[h][1] = fma2(sp, (ull)e2.y, pa[h][1]);
                }
            }
        }
    }
    __syncthreads();                 // e_s reads done; alias for partials
    float4* part = (float4*)e_s;     // [jg][h][c4] float4 = 32 KB
#pragma unroll
    for (int h = 0; h < HH; h++) {
        const float2 A = unpack2(pa[h][0]);
        const float2 B = unpack2(pa[h][1]);
        part[(jg * 8 + h) * 16 + c4] = make_float4(A.x, A.y, B.x, B.y);
    }
    __syncthreads();
    if (t < 128) {                   // h = t>>4, c4m = t&15
        const int h = t >> 4;
        const int c4m = t & 15;
        float4 s = part[h * 16 + c4m];
#pragma unroll
        for (int g = 1; g < 16; g++) {
            const float4 p = part[(g * 8 + h) * 16 + c4m];
            s.x += p.x; s.y += p.y; s.z += p.z; s.w += p.w;
        }
        *(float4*)&g_aggu[((size_t)(half * NROW + i) * HH + h) * ED + c4m * 4] = s;
    }
}

// ---------------------------------------------------------------------------
// Kernel C: out = inv * (esim @ v + aggu @ We) + rs * be.
// grid (32 i-tiles of 16, 8 heads) = 256 blocks (2/SM), software-pipelined
// register prefetch of j-chunks. No atomics.
// ---------------------------------------------------------------------------
__global__ __launch_bounds__(256, 2) void outv_kernel(
    const float* __restrict__ We, const float* __restrict__ be,
    float* __restrict__ out)
{
    __shared__ float a_s[16 * 128];                   // esim tile
    __shared__ __align__(8) float v_sT[32 * VPAD];    // v transposed [d][j]
    __shared__ float we_s[ED * DD];                   // [c][d]
    __shared__ float agg_s[16 * ED];                  // [r][c]
    __shared__ float inv_s[16], rs_s[16];

    const int t = threadIdx.x;
    const int i0 = blockIdx.x * 16;
    const int h  = blockIdx.y;
    const int d  = t & 31;
    const int r0 = t >> 5;          // 0..7 -> rows r0, r0+8

    // stage We, combined agg, inv/rs
#pragma unroll
    for (int k = 0; k < 8; k++) {
        const int idx = t + k * 256;                  // c = idx>>5, dd = idx&31
        we_s[idx] = We[(idx >> 5) * INNER + h * DD + (idx & 31)];
    }
#pragma unroll
    for (int k = 0; k < 4; k++) {
        const int idx = t + k * 256;                  // r = idx>>6, c = idx&63
        const int rr = idx >> 6, c = idx & 63;
        agg_s[idx] = g_aggu[((size_t)(i0 + rr) * HH + h) * ED + c]
                   + g_aggu[((size_t)(NROW + i0 + rr) * HH + h) * ED + c];
    }
    if (t < 16) {
        const float s = g_sump[h * NROW + i0 + t]
                      + g_sump[HH * NROW + h * NROW + i0 + t];
        inv_s[t] = s > 0.f ? 1.f / s : 0.f;
        rs_s[t]  = s > 0.f ? 1.f : 0.f;
    }

    // prefetch chunk 0 into registers (overlaps the staging above)
    float4 ar[2], vr[4];
#pragma unroll
    for (int f = 0; f < 2; f++) {
        const int idx = t + f * 256;                  // row = idx>>5 (0..15)
        ar[f] = *(const float4*)&g_esim[((size_t)h * NROW + i0 + (idx >> 5)) * NROW
                                        + (idx & 31) * 4];
    }
#pragma unroll
    for (int f = 0; f < 4; f++) {
        const int idx = t + f * 256;                  // row = idx>>3 (0..127)
        vr[f] = *(const float4*)&g_v[(size_t)(idx >> 3) * INNER + h * DD + (idx & 7) * 4];
    }
    __syncthreads();

    // edge term (unnormalized)
    float acc[2] = {0.f, 0.f};
#pragma unroll 8
    for (int c = 0; c < ED; c++) {
        const float w = we_s[c * DD + d];
        acc[0] = fmaf(agg_s[r0 * ED + c], w, acc[0]);
        acc[1] = fmaf(agg_s[(r0 + 8) * ED + c], w, acc[1]);
    }

    // v term: 4 chunks of 128 j, register-prefetch pipeline
    ull acc2[2] = {0ull, 0ull};
    for (int ch = 0; ch < 4; ch++) {
        __syncthreads();                              // prev compute done
#pragma unroll
        for (int f = 0; f < 2; f++) {
            const int idx = t + f * 256;
            *(float4*)&a_s[(idx >> 5) * 128 + (idx & 31) * 4] = ar[f];
        }
#pragma unroll
        for (int f = 0; f < 4; f++) {
            const int idx = t + f * 256;
            const int row = idx >> 3, c4 = idx & 7;
            v_sT[(c4 * 4 + 0) * VPAD + row] = vr[f].x;
            v_sT[(c4 * 4 + 1) * VPAD + row] = vr[f].y;
            v_sT[(c4 * 4 + 2) * VPAD + row] = vr[f].z;
            v_sT[(c4 * 4 + 3) * VPAD + row] = vr[f].w;
        }
        __syncthreads();

        if (ch < 3) {                                 // prefetch next chunk
            const int j0n = (ch + 1) * 128;
#pragma unroll
            for (int f = 0; f < 2; f++) {
                const int idx = t + f * 256;
                ar[f] = *(const float4*)&g_esim[((size_t)h * NROW + i0 + (idx >> 5)) * NROW
                                                + j0n + (idx & 31) * 4];
            }
#pragma unroll
            for (int f = 0; f < 4; f++) {
                const int idx = t + f * 256;
                vr[f] = *(const float4*)&g_v[(size_t)(j0n + (idx >> 3)) * INNER
                                             + h * DD + (idx & 7) * 4];
            }
        }

#pragma unroll 8
        for (int jp = 0; jp < 64; jp++) {
            const ull v2 = *(const ull*)&v_sT[d * VPAD + jp * 2];
            acc2[0] = fma2(*(const ull*)&a_s[r0 * 128 + jp * 2], v2, acc2[0]);
            acc2[1] = fma2(*(const ull*)&a_s[(r0 + 8) * 128 + jp * 2], v2, acc2[1]);
        }
    }

    const float bev = be[h * DD + d];
#pragma unroll
    for (int m = 0; m < 2; m++) {
        const int r = r0 + m * 8;
        out[(i0 + r) * INNER + h * DD + d] =
            fmaf(rs_s[r], bev, (acc[m] + hsum2(acc2[m])) * inv_s[r]);
    }
}

// ---------------------------------------------------------------------------
extern "C" void kernel_launch(void* const* d_in, const int* in_sizes, int n_in,
                              void* d_out, int out_size)
{
    const float* nodes = (const float*)d_in[0];
    const float* edges = (const float*)d_in[1];
    const int*   adj   = (const int*)d_in[2];
    const float* Wq    = (const float*)d_in[3];
    const float* bq    = (const float*)d_in[4];
    const float* Wk    = (const float*)d_in[5];
    const float* bk    = (const float*)d_in[6];
    const float* Wv    = (const float*)d_in[7];
    const float* bv    = (const float*)d_in[8];
    const float* We    = (const float*)d_in[9];
    const float* be    = (const float*)d_in[10];
    float* out = (float*)d_out;

    cudaFuncSetAttribute(simagg_kernel,
                         cudaFuncAttributeMaxDynamicSharedMemorySize, HSMEM);

    proj_kernel<<<128, 256>>>(nodes, Wq, bq, Wk, bk, Wv, bv, We, be);
    qk_kernel<<<dim3(16, 16, 8), 256>>>();
    simagg_kernel<<<1024, 256, HSMEM>>>(edges, adj);
    outv_kernel<<<dim3(32, 8), 256>>>(We, be, out);
}